// round 1
// baseline (speedup 1.0000x reference)
#include <cuda_runtime.h>

#define FULL 0xffffffffu

constexpr int Bn = 16, Hn = 128, Wn = 128, Sn = 4, Cn = 64;
constexpr int SCn = Sn * Cn;                // 256
constexpr int NPIX = Bn * Hn * Wn;          // 262144

// Scratch (static device arrays -- allocation-free rule)
__device__ float g_xpre[(size_t)Cn * NPIX];     // layout [b][c][y][x]  (channel-major for conv)
__device__ float g_hpost[(size_t)NPIX * Sn];    // [pix][4]

union F2U { float2 f; unsigned long long u; };

__device__ __forceinline__ unsigned long long pack2(float v) {
    F2U t; t.f = make_float2(v, v); return t.u;
}
__device__ __forceinline__ void ffma2(unsigned long long& d, unsigned long long a, unsigned long long b) {
    asm("fma.rn.f32x2 %0, %1, %2, %0;" : "+l"(d) : "l"(a), "l"(b));
}

// ---------------------------------------------------------------------------
// Kernel 1: gates. One warp per pixel (4 pixels sequentially per warp).
// Computes RMSNorm-folded projections, sigmoid/sinkhorn/sigmoid gates,
// writes out = einsum(h_res, x), x_pre (channel-major), h_post.
// ---------------------------------------------------------------------------
__global__ void __launch_bounds__(256) gates_kernel(
    const float* __restrict__ x,
    const float* __restrict__ w_pre, const float* __restrict__ w_post, const float* __restrict__ w_res,
    const float* __restrict__ b_pre, const float* __restrict__ b_res, const float* __restrict__ b_post,
    const float* __restrict__ alpha_pre, const float* __restrict__ alpha_res, const float* __restrict__ alpha_post,
    const float* __restrict__ rms_w,
    float* __restrict__ out)
{
    // w_t[f][o]: transposed effective weights (alpha & rms_w folded), stride 28 for
    // conflict-free 128-bit LDS. Order: o 0..3 = pre, 4..19 = res, 20..23 = post.
    __shared__ __align__(16) float w_t[SCn][28];
    __shared__ float b_all[24];
    __shared__ float s_xp[64][33];   // x_pre transpose stage: [c][x_local]

    const int tid = threadIdx.x;
    {
        const int f = tid;  // 0..255 == feature
        const float rw = rms_w[f];
        const float apre = alpha_pre[0], ares = alpha_res[0], apost = alpha_post[0];
#pragma unroll
        for (int o = 0; o < 4; o++)  w_t[f][o]      = apre  * w_pre[o * SCn + f]  * rw;
#pragma unroll
        for (int o = 0; o < 16; o++) w_t[f][4 + o]  = ares  * w_res[o * SCn + f]  * rw;
#pragma unroll
        for (int o = 0; o < 4; o++)  w_t[f][20 + o] = apost * w_post[o * SCn + f] * rw;
        if (tid < 4)       b_all[tid] = b_pre[tid];
        else if (tid < 20) b_all[tid] = b_res[tid - 4];
        else if (tid < 24) b_all[tid] = b_post[tid - 20];
    }
    __syncthreads();

    const int lane  = tid & 31;
    const int warp  = tid >> 5;
    const int idx16 = lane & 15;            // = s*4 + t

    for (int i = 0; i < 4; ++i) {
        const size_t pix = (size_t)blockIdx.x * 32 + warp * 4 + i;
        const float* xp = x + pix * SCn;

        // xv[k] = x[pix, 32k + lane]  (coalesced)
        float xv[8];
#pragma unroll
        for (int k = 0; k < 8; k++) xv[k] = xp[k * 32 + lane];

        // RMS
        float ss = 0.f;
#pragma unroll
        for (int k = 0; k < 8; k++) ss += xv[k] * xv[k];
#pragma unroll
        for (int off = 16; off; off >>= 1) ss += __shfl_xor_sync(FULL, ss, off);
        const float rms = rsqrtf(ss * (1.0f / 256.0f) + 1.1920929e-07f);

        // 24 dot products, packed f32x2 FMA
        unsigned long long acc[12];
#pragma unroll
        for (int j = 0; j < 12; j++) acc[j] = 0ull;
#pragma unroll
        for (int k = 0; k < 8; k++) {
            const unsigned long long xx = pack2(xv[k]);
            const ulonglong2* w2 = reinterpret_cast<const ulonglong2*>(&w_t[k * 32 + lane][0]);
#pragma unroll
            for (int q = 0; q < 6; q++) {
                ulonglong2 w = w2[q];
                ffma2(acc[2 * q],     xx, w.x);   // outputs (4q, 4q+1)
                ffma2(acc[2 * q + 1], xx, w.y);   // outputs (4q+2, 4q+3)
            }
        }
        float s24[24];
#pragma unroll
        for (int j = 0; j < 12; j++) {
            F2U t; t.u = acc[j];
            s24[2 * j] = t.f.x; s24[2 * j + 1] = t.f.y;
        }
        // warp allreduce of 24 values
#pragma unroll
        for (int o = 0; o < 24; o++) {
#pragma unroll
            for (int off = 16; off; off >>= 1)
                s24[o] += __shfl_xor_sync(FULL, s24[o], off);
        }

        // ---- Sinkhorn over 4x4 (lanes 0..15 hold element idx16 = s*4+t; 16..31 mirror)
        float h = s24[4 + idx16] * rms + b_all[4 + idx16];
        float m = h;
#pragma unroll
        for (int off = 1; off < 16; off <<= 1)
            m = fmaxf(m, __shfl_xor_sync(FULL, m, off));
        h = __expf(h - m);
        for (int it = 0; it < 20; ++it) {
            float cs = h + __shfl_xor_sync(FULL, h, 4);   // sum over s (axis -2)
            cs += __shfl_xor_sync(FULL, cs, 8);
            h = __fdividef(h, cs + 1e-6f);
            float rs = h + __shfl_xor_sync(FULL, h, 1);   // sum over t (axis -1)
            rs += __shfl_xor_sync(FULL, rs, 2);
            h = __fdividef(h, rs + 1e-6f);
        }
        float hr[16];
#pragma unroll
        for (int j = 0; j < 16; j++) hr[j] = __shfl_sync(FULL, h, j);

        // h_pre (sigmoid)
        float hp[4];
#pragma unroll
        for (int s = 0; s < 4; s++)
            hp[s] = __fdividef(1.0f, 1.0f + __expf(-(s24[s] * rms + b_all[s])));

        // h_post (2*sigmoid) -> global
        if (lane < 4) {
            const float z = s24[20 + lane] * rms + b_all[20 + lane];
            g_hpost[pix * 4 + lane] = __fdividef(2.0f, 1.0f + __expf(-z));
        }

        // out[s,c] = sum_t h_res[s,t] * x[t,c]; feature f=32k+lane -> s=k>>1, xv[2t+(k&1)]
        float* op = out + pix * SCn;
#pragma unroll
        for (int k = 0; k < 8; k++) {
            const int s = k >> 1, p = k & 1;
            const float o = hr[4 * s + 0] * xv[0 + p] + hr[4 * s + 1] * xv[2 + p]
                          + hr[4 * s + 2] * xv[4 + p] + hr[4 * s + 3] * xv[6 + p];
            op[k * 32 + lane] = o;
        }

        // x_pre[c] = sum_s h_pre[s]*x[s,c]; stage into shared for channel-major write
        const float xp0 = hp[0] * xv[0] + hp[1] * xv[2] + hp[2] * xv[4] + hp[3] * xv[6]; // c = lane
        const float xp1 = hp[0] * xv[1] + hp[1] * xv[3] + hp[2] * xv[5] + hp[3] * xv[7]; // c = lane+32
        const int xl = warp * 4 + i;    // block covers 32 consecutive x of one row
        s_xp[lane][xl]      = xp0;
        s_xp[lane + 32][xl] = xp1;
    }

    __syncthreads();
    // coalesced channel-major writeout of x_pre
    {
        const size_t pix0 = (size_t)blockIdx.x * 32;
        const int b  = (int)(pix0 >> 14);
        const int y  = (int)((pix0 >> 7) & 127);
        const int x0 = (int)(pix0 & 127);
#pragma unroll
        for (int e = tid; e < 64 * 32; e += 256) {
            const int c = e >> 5, xl = e & 31;
            g_xpre[(((size_t)b * 64 + c) * 128 + y) * 128 + x0 + xl] = s_xp[c][xl];
        }
    }
}

// ---------------------------------------------------------------------------
// Kernel 2: 3x3 conv (fp32, packed f32x2 FMA) + gated residual epilogue.
// Tile 8x32 output pixels, 1 thread per pixel, 64 output channels in regs.
// ---------------------------------------------------------------------------
constexpr int TILE_H = 8, TILE_W = 32;
constexpr int IN_H = TILE_H + 2, IN_W = TILE_W + 2;       // 10 x 34
constexpr int CI_CHUNK = 16;
constexpr int SX_ELEMS = CI_CHUNK * IN_H * IN_W;          // 5440
constexpr int SW_ELEMS = 9 * CI_CHUNK * 64;               // 9216
constexpr int SL_STRIDE = 65;
constexpr int SL_ELEMS = 256 * SL_STRIDE;                 // 16640
constexpr int SMEM_FLOATS = (SX_ELEMS + SW_ELEMS) > SL_ELEMS ? (SX_ELEMS + SW_ELEMS) : SL_ELEMS;

__global__ void __launch_bounds__(256, 2) conv_kernel(
    const float* __restrict__ conv_w,
    float* __restrict__ out)
{
    extern __shared__ __align__(16) float smem[];
    float* s_x = smem;                  // [CI_CHUNK][IN_H][IN_W]
    float* s_w = smem + SX_ELEMS;       // [9][CI_CHUNK][64]

    const int tid = threadIdx.x;
    const int px = tid & 31, py = tid >> 5;
    const int b = blockIdx.z;
    const int gy0 = blockIdx.y * TILE_H;
    const int gx0 = blockIdx.x * TILE_W;

    unsigned long long acc[32];   // 64 output channels as 32 f32x2
#pragma unroll
    for (int j = 0; j < 32; j++) acc[j] = 0ull;

    for (int chunk = 0; chunk < Cn / CI_CHUNK; ++chunk) {
        __syncthreads();
        // load x_pre halo chunk (channel-major source -> coalesced in x)
        for (int e = tid; e < SX_ELEMS; e += 256) {
            const int ci  = e / (IN_H * IN_W);
            const int rem = e % (IN_H * IN_W);
            const int iy = rem / IN_W, ix = rem % IN_W;
            const int gy = gy0 + iy - 1, gx = gx0 + ix - 1;
            float v = 0.f;
            if ((unsigned)gy < 128u && (unsigned)gx < 128u)
                v = g_xpre[(((size_t)b * 64 + chunk * CI_CHUNK + ci) * 128 + gy) * 128 + gx];
            s_x[e] = v;
        }
        // load weight chunk: conv_w is HWIO [3][3][64][64]
        for (int e = tid; e < SW_ELEMS; e += 256) {
            const int co = e & 63;
            const int ci = (e >> 6) & (CI_CHUNK - 1);
            const int kk = e >> 10;   // e / (64*CI_CHUNK)
            s_w[e] = conv_w[((size_t)kk * 64 + chunk * CI_CHUNK + ci) * 64 + co];
        }
        __syncthreads();

        for (int kk = 0; kk < 9; ++kk) {
            const int ky = kk / 3, kx = kk - ky * 3;
            const float* xcol = s_x + (py + ky) * IN_W + (px + kx);
            const ulonglong2* wrow = reinterpret_cast<const ulonglong2*>(s_w + kk * CI_CHUNK * 64);
#pragma unroll
            for (int ci = 0; ci < CI_CHUNK; ++ci) {
                const float xvv = xcol[ci * (IN_H * IN_W)];
                const unsigned long long xx = pack2(xvv);
#pragma unroll
                for (int j = 0; j < 16; ++j) {
                    ulonglong2 w = wrow[ci * 16 + j];
                    ffma2(acc[2 * j],     xx, w.x);   // channels (4j, 4j+1)
                    ffma2(acc[2 * j + 1], xx, w.y);   // channels (4j+2, 4j+3)
                }
            }
        }
    }

    // stage layer_out through shared for coalesced epilogue
    __syncthreads();
    float* s_l = smem;   // [256][65]
#pragma unroll
    for (int j = 0; j < 32; j++) {
        F2U t; t.u = acc[j];
        s_l[tid * SL_STRIDE + 2 * j]     = t.f.x;
        s_l[tid * SL_STRIDE + 2 * j + 1] = t.f.y;
    }
    __syncthreads();

    // epilogue: out[pix, s*64+c] += h_post[pix,s] * layer_out[pix,c]
    const int lane = tid & 31, wrp = tid >> 5;
    const int gy = gy0 + wrp;          // warp w owns output row py == w
    for (int pp = 0; pp < 32; ++pp) {
        const size_t pix = ((size_t)b * 128 + gy) * 128 + (gx0 + pp);
        const float* lrow = s_l + (wrp * 32 + pp) * SL_STRIDE;
        float* op = out + pix * SCn;
        float hpv[4];
#pragma unroll
        for (int s = 0; s < 4; s++) hpv[s] = g_hpost[pix * 4 + s];
#pragma unroll
        for (int k = 0; k < 8; k++) {
            const float l = lrow[(k & 1) * 32 + lane];
            op[k * 32 + lane] += hpv[k >> 1] * l;
        }
    }
}

// ---------------------------------------------------------------------------
extern "C" void kernel_launch(void* const* d_in, const int* in_sizes, int n_in,
                              void* d_out, int out_size)
{
    const float* x       = (const float*)d_in[0];
    const float* w_pre   = (const float*)d_in[1];
    const float* w_post  = (const float*)d_in[2];
    const float* w_res   = (const float*)d_in[3];
    const float* b_pre   = (const float*)d_in[4];
    const float* b_res   = (const float*)d_in[5];
    const float* b_post  = (const float*)d_in[6];
    const float* a_pre   = (const float*)d_in[7];
    const float* a_res   = (const float*)d_in[8];
    const float* a_post  = (const float*)d_in[9];
    const float* rms_w   = (const float*)d_in[10];
    const float* conv_w  = (const float*)d_in[11];
    float* out = (float*)d_out;

    gates_kernel<<<NPIX / 32, 256>>>(x, w_pre, w_post, w_res,
                                     b_pre, b_res, b_post,
                                     a_pre, a_res, a_post,
                                     rms_w, out);

    cudaFuncSetAttribute(conv_kernel, cudaFuncAttributeMaxDynamicSharedMemorySize,
                         SMEM_FLOATS * (int)sizeof(float));
    conv_kernel<<<dim3(Wn / TILE_W, Hn / TILE_H, Bn), 256, SMEM_FLOATS * sizeof(float)>>>(conv_w, out);
}

// round 2
// speedup vs baseline: 1.2793x; 1.2793x over previous
#include <cuda_runtime.h>

#define FULL 0xffffffffu

constexpr int Bn = 16, Hn = 128, Wn = 128, Sn = 4, Cn = 64;
constexpr int SCn = Sn * Cn;                // 256
constexpr int NPIX = Bn * Hn * Wn;          // 262144

// Scratch (static device arrays -- allocation-free rule)
__device__ float g_xpre[(size_t)Cn * NPIX];                 // [b][c][y][x] channel-major
__device__ float g_hpost[(size_t)NPIX * Sn];                // [pix][4]
__device__ __align__(16) float g_hres[(size_t)NPIX * 16];   // [pix][16] raw -> sinkhorn'd

union F2U { float2 f; unsigned long long u; };

__device__ __forceinline__ unsigned long long pack2(float v) {
    F2U t; t.f = make_float2(v, v); return t.u;
}
__device__ __forceinline__ void ffma2(unsigned long long& d, unsigned long long a, unsigned long long b) {
    asm("fma.rn.f32x2 %0, %1, %2, %0;" : "+l"(d) : "l"(a), "l"(b));
}
__device__ __forceinline__ void add2(unsigned long long& d, unsigned long long o) {
    asm("add.rn.f32x2 %0, %0, %1;" : "+l"(d) : "l"(o));
}

// ---------------------------------------------------------------------------
// Kernel 1: projections. One warp per pixel (4 pixels sequentially per warp).
// RMSNorm-folded matvec -> writes raw h_res pre-activations, h_post gate,
// and x_pre (channel-major). No sinkhorn, no einsum here.
// ---------------------------------------------------------------------------
__global__ void __launch_bounds__(256) proj_kernel(
    const float* __restrict__ x,
    const float* __restrict__ w_pre, const float* __restrict__ w_post, const float* __restrict__ w_res,
    const float* __restrict__ b_pre, const float* __restrict__ b_res, const float* __restrict__ b_post,
    const float* __restrict__ alpha_pre, const float* __restrict__ alpha_res, const float* __restrict__ alpha_post,
    const float* __restrict__ rms_w)
{
    __shared__ __align__(16) float w_t[SCn][28];  // o: 0..3 pre, 4..19 res, 20..23 post
    __shared__ float b_all[24];
    __shared__ float s_xp[64][33];                 // x_pre transpose stage [c][x_local]

    const int tid = threadIdx.x;
    {
        const int f = tid;
        const float rw = rms_w[f];
        const float apre = alpha_pre[0], ares = alpha_res[0], apost = alpha_post[0];
#pragma unroll
        for (int o = 0; o < 4; o++)  w_t[f][o]      = apre  * w_pre[o * SCn + f]  * rw;
#pragma unroll
        for (int o = 0; o < 16; o++) w_t[f][4 + o]  = ares  * w_res[o * SCn + f]  * rw;
#pragma unroll
        for (int o = 0; o < 4; o++)  w_t[f][20 + o] = apost * w_post[o * SCn + f] * rw;
        if (tid < 4)       b_all[tid] = b_pre[tid];
        else if (tid < 20) b_all[tid] = b_res[tid - 4];
        else if (tid < 24) b_all[tid] = b_post[tid - 20];
    }
    __syncthreads();

    const int lane = tid & 31;
    const int warp = tid >> 5;

    for (int i = 0; i < 4; ++i) {
        const size_t pix = (size_t)blockIdx.x * 32 + warp * 4 + i;
        const float* xp = x + pix * SCn;

        float xv[8];
#pragma unroll
        for (int k = 0; k < 8; k++) xv[k] = xp[k * 32 + lane];

        float ss = 0.f;
#pragma unroll
        for (int k = 0; k < 8; k++) ss += xv[k] * xv[k];
#pragma unroll
        for (int off = 16; off; off >>= 1) ss += __shfl_xor_sync(FULL, ss, off);
        const float rms = rsqrtf(ss * (1.0f / 256.0f) + 1.1920929e-07f);

        // 24 dot products as 12 packed f32x2 accumulators
        unsigned long long acc[12];
#pragma unroll
        for (int j = 0; j < 12; j++) acc[j] = 0ull;
#pragma unroll
        for (int k = 0; k < 8; k++) {
            const unsigned long long xx = pack2(xv[k]);
            const ulonglong2* w2 = reinterpret_cast<const ulonglong2*>(&w_t[k * 32 + lane][0]);
#pragma unroll
            for (int q = 0; q < 6; q++) {
                ulonglong2 w = w2[q];
                ffma2(acc[2 * q],     xx, w.x);
                ffma2(acc[2 * q + 1], xx, w.y);
            }
        }
        // butterfly allreduce on packed pairs (2 shfl.32 + 1 add.f32x2 per value-level)
#pragma unroll
        for (int j = 0; j < 12; j++) {
#pragma unroll
            for (int off = 16; off; off >>= 1) {
                unsigned lo = __shfl_xor_sync(FULL, (unsigned)acc[j], off);
                unsigned hi = __shfl_xor_sync(FULL, (unsigned)(acc[j] >> 32), off);
                add2(acc[j], ((unsigned long long)hi << 32) | lo);
            }
        }
        float s24[24];
#pragma unroll
        for (int j = 0; j < 12; j++) {
            F2U t; t.u = acc[j];
            s24[2 * j] = t.f.x; s24[2 * j + 1] = t.f.y;
        }

        // raw h_res pre-activations -> global (sinkhorn kernel finishes them)
        if (lane < 16) g_hres[pix * 16 + lane] = s24[4 + lane] * rms + b_all[4 + lane];

        // h_post = 2*sigmoid
        if (lane < 4) {
            const float z = s24[20 + lane] * rms + b_all[20 + lane];
            g_hpost[pix * 4 + lane] = __fdividef(2.0f, 1.0f + __expf(-z));
        }

        // h_pre (sigmoid) used immediately for x_pre
        float hp[4];
#pragma unroll
        for (int s = 0; s < 4; s++)
            hp[s] = __fdividef(1.0f, 1.0f + __expf(-(s24[s] * rms + b_all[s])));

        const float xp0 = hp[0] * xv[0] + hp[1] * xv[2] + hp[2] * xv[4] + hp[3] * xv[6]; // c = lane
        const float xp1 = hp[0] * xv[1] + hp[1] * xv[3] + hp[2] * xv[5] + hp[3] * xv[7]; // c = lane+32
        const int xl = warp * 4 + i;
        s_xp[lane][xl]      = xp0;
        s_xp[lane + 32][xl] = xp1;
    }

    __syncthreads();
    {
        const size_t pix0 = (size_t)blockIdx.x * 32;
        const int b  = (int)(pix0 >> 14);
        const int y  = (int)((pix0 >> 7) & 127);
        const int x0 = (int)(pix0 & 127);
#pragma unroll
        for (int e = tid; e < 64 * 32; e += 256) {
            const int c = e >> 5, xl = e & 31;
            g_xpre[(((size_t)b * 64 + c) * 128 + y) * 128 + x0 + xl] = s_xp[c][xl];
        }
    }
}

// ---------------------------------------------------------------------------
// Kernel 2: Sinkhorn, one thread per pixel, all 16 values in registers.
// ---------------------------------------------------------------------------
__global__ void __launch_bounds__(256) sinkhorn_kernel()
{
    const size_t pix = (size_t)blockIdx.x * 256 + threadIdx.x;
    float4* hp = reinterpret_cast<float4*>(g_hres + pix * 16);
    float4 q0 = hp[0], q1 = hp[1], q2 = hp[2], q3 = hp[3];
    float v[16] = {q0.x, q0.y, q0.z, q0.w, q1.x, q1.y, q1.z, q1.w,
                   q2.x, q2.y, q2.z, q2.w, q3.x, q3.y, q3.z, q3.w};
    float m = v[0];
#pragma unroll
    for (int j = 1; j < 16; j++) m = fmaxf(m, v[j]);
#pragma unroll
    for (int j = 0; j < 16; j++) v[j] = __expf(v[j] - m);

    for (int it = 0; it < 20; ++it) {
#pragma unroll
        for (int t = 0; t < 4; t++) {
            const float cs = v[t] + v[4 + t] + v[8 + t] + v[12 + t];
            const float inv = __fdividef(1.0f, cs + 1e-6f);
            v[t] *= inv; v[4 + t] *= inv; v[8 + t] *= inv; v[12 + t] *= inv;
        }
#pragma unroll
        for (int s = 0; s < 4; s++) {
            const float rs = v[4 * s] + v[4 * s + 1] + v[4 * s + 2] + v[4 * s + 3];
            const float inv = __fdividef(1.0f, rs + 1e-6f);
            v[4 * s] *= inv; v[4 * s + 1] *= inv; v[4 * s + 2] *= inv; v[4 * s + 3] *= inv;
        }
    }
    hp[0] = make_float4(v[0], v[1], v[2], v[3]);
    hp[1] = make_float4(v[4], v[5], v[6], v[7]);
    hp[2] = make_float4(v[8], v[9], v[10], v[11]);
    hp[3] = make_float4(v[12], v[13], v[14], v[15]);
}

// ---------------------------------------------------------------------------
// Kernel 3: 3x3 conv (f32x2 FMA, 4px x 16ch per thread) + full epilogue:
// out = einsum(h_res, x) + h_post * layer_out
// ---------------------------------------------------------------------------
constexpr int TILE_H = 8, TILE_W = 32;
constexpr int IN_H = TILE_H + 2;                    // 10
constexpr int IN_W2 = 36;                           // padded (mult of 4) halo width
constexpr int CI_CHUNK = 16;
constexpr int SX_ELEMS = CI_CHUNK * IN_H * IN_W2;   // 5760
constexpr int SW_ELEMS = 9 * CI_CHUNK * 64;         // 9216
constexpr int SL_STRIDE = 66;
constexpr int SL_ELEMS = 256 * SL_STRIDE;           // 16896
constexpr int SMEM_FLOATS = (SX_ELEMS + SW_ELEMS) > SL_ELEMS ? (SX_ELEMS + SW_ELEMS) : SL_ELEMS;

__global__ void __launch_bounds__(256, 2) conv_kernel(
    const float* __restrict__ conv_w,
    const float* __restrict__ x,
    float* __restrict__ out)
{
    extern __shared__ __align__(16) float smem[];
    float* s_x = smem;                 // [CI_CHUNK][IN_H][IN_W2]
    float* s_w = smem + SX_ELEMS;      // [9][CI_CHUNK][64]

    const int tid = threadIdx.x;
    const int cg  = tid >> 6;          // 16-channel group 0..3
    const int r   = tid & 63;
    const int py  = r >> 3;            // 0..7
    const int x0  = (r & 7) * 4;       // 0,4,...,28
    const int b   = blockIdx.z;
    const int gy0 = blockIdx.y * TILE_H;
    const int gx0 = blockIdx.x * TILE_W;

    unsigned long long acc[4][8];      // 4 pixels x 16 channels (8 f32x2)
#pragma unroll
    for (int p = 0; p < 4; p++)
#pragma unroll
        for (int j = 0; j < 8; j++) acc[p][j] = 0ull;

#pragma unroll 1
    for (int chunk = 0; chunk < Cn / CI_CHUNK; ++chunk) {
        __syncthreads();
        for (int e = tid; e < SX_ELEMS; e += 256) {
            const int ci  = e / (IN_H * IN_W2);
            const int rem = e - ci * (IN_H * IN_W2);
            const int iy = rem / IN_W2, ix = rem - iy * IN_W2;
            const int gy = gy0 + iy - 1, gx = gx0 + ix - 1;
            float v = 0.f;
            if ((unsigned)gy < 128u && (unsigned)gx < 128u)
                v = g_xpre[(((size_t)b * 64 + chunk * CI_CHUNK + ci) * 128 + gy) * 128 + gx];
            s_x[e] = v;
        }
        for (int e = tid; e < SW_ELEMS; e += 256) {
            const int co = e & 63;
            const int ci = (e >> 6) & (CI_CHUNK - 1);
            const int kk = e >> 10;
            s_w[e] = conv_w[((size_t)kk * 64 + chunk * CI_CHUNK + ci) * 64 + co];
        }
        __syncthreads();

#pragma unroll 1
        for (int ci = 0; ci < CI_CHUNK; ++ci) {
#pragma unroll
            for (int ky = 0; ky < 3; ++ky) {
                const float* xr = s_x + (ci * IN_H + py + ky) * IN_W2 + x0;
                const float4 a0 = *reinterpret_cast<const float4*>(xr);
                const float2 a1 = *reinterpret_cast<const float2*>(xr + 4);
                const float xa[6] = {a0.x, a0.y, a0.z, a0.w, a1.x, a1.y};
#pragma unroll
                for (int kx = 0; kx < 3; ++kx) {
                    const ulonglong2* wr = reinterpret_cast<const ulonglong2*>(
                        s_w + ((ky * 3 + kx) * CI_CHUNK + ci) * 64 + cg * 16);
                    const ulonglong2 wA = wr[0], wB = wr[1];
#pragma unroll
                    for (int p = 0; p < 4; ++p) {
                        const unsigned long long xx = pack2(xa[p + kx]);
                        ffma2(acc[p][0], xx, wA.x);
                        ffma2(acc[p][1], xx, wA.y);
                        ffma2(acc[p][2], xx, wB.x);
                        ffma2(acc[p][3], xx, wB.y);
                        ffma2(acc[p][4], xx, wr[2].x);
                        ffma2(acc[p][5], xx, wr[2].y);
                        ffma2(acc[p][6], xx, wr[3].x);
                        ffma2(acc[p][7], xx, wr[3].y);
                    }
                }
            }
        }
    }

    // stage layer_out in shared: s_l[pixel_local][channel]
    __syncthreads();
    float* s_l = smem;   // [256][SL_STRIDE]
#pragma unroll
    for (int p = 0; p < 4; ++p) {
        float* dst = s_l + (py * 32 + x0 + p) * SL_STRIDE + cg * 16;
#pragma unroll
        for (int j = 0; j < 8; ++j) {
            F2U t; t.u = acc[p][j];
            *reinterpret_cast<float2*>(dst + 2 * j) = t.f;
        }
    }
    __syncthreads();

    // epilogue: out = einsum(h_res, x) + h_post * layer_out
    const int lane = tid & 31, wrp = tid >> 5;
    const int gy = gy0 + wrp;
    for (int pp = 0; pp < 32; ++pp) {
        const size_t pix = ((size_t)b * 128 + gy) * 128 + (gx0 + pp);
        const float* xp = x + pix * SCn;
        const float4* hq = reinterpret_cast<const float4*>(g_hres + pix * 16);
        const float4 h0 = hq[0], h1 = hq[1], h2 = hq[2], h3 = hq[3];
        const float4 hpst = *reinterpret_cast<const float4*>(g_hpost + pix * 4);
        const float* lrow = s_l + (wrp * 32 + pp) * SL_STRIDE;
        float* op = out + pix * SCn;
#pragma unroll
        for (int p2 = 0; p2 < 2; ++p2) {
            const int c = p2 * 32 + lane;
            const float l  = lrow[c];
            const float t0 = xp[c];
            const float t1 = xp[64 + c];
            const float t2 = xp[128 + c];
            const float t3 = xp[192 + c];
            op[c]       = h0.x * t0 + h0.y * t1 + h0.z * t2 + h0.w * t3 + hpst.x * l;
            op[64 + c]  = h1.x * t0 + h1.y * t1 + h1.z * t2 + h1.w * t3 + hpst.y * l;
            op[128 + c] = h2.x * t0 + h2.y * t1 + h2.z * t2 + h2.w * t3 + hpst.z * l;
            op[192 + c] = h3.x * t0 + h3.y * t1 + h3.z * t2 + h3.w * t3 + hpst.w * l;
        }
    }
}

// ---------------------------------------------------------------------------
extern "C" void kernel_launch(void* const* d_in, const int* in_sizes, int n_in,
                              void* d_out, int out_size)
{
    const float* x       = (const float*)d_in[0];
    const float* w_pre   = (const float*)d_in[1];
    const float* w_post  = (const float*)d_in[2];
    const float* w_res   = (const float*)d_in[3];
    const float* b_pre   = (const float*)d_in[4];
    const float* b_res   = (const float*)d_in[5];
    const float* b_post  = (const float*)d_in[6];
    const float* a_pre   = (const float*)d_in[7];
    const float* a_res   = (const float*)d_in[8];
    const float* a_post  = (const float*)d_in[9];
    const float* rms_w   = (const float*)d_in[10];
    const float* conv_w  = (const float*)d_in[11];
    float* out = (float*)d_out;

    proj_kernel<<<NPIX / 32, 256>>>(x, w_pre, w_post, w_res,
                                    b_pre, b_res, b_post,
                                    a_pre, a_res, a_post, rms_w);

    sinkhorn_kernel<<<NPIX / 256, 256>>>();

    cudaFuncSetAttribute(conv_kernel, cudaFuncAttributeMaxDynamicSharedMemorySize,
                         SMEM_FLOATS * (int)sizeof(float));
    conv_kernel<<<dim3(Wn / TILE_W, Hn / TILE_H, Bn), 256, SMEM_FLOATS * sizeof(float)>>>(
        conv_w, x, out);
}

// round 3
// speedup vs baseline: 1.3737x; 1.0738x over previous
#include <cuda_runtime.h>

#define FULL 0xffffffffu

constexpr int Bn = 16, Hn = 128, Wn = 128, Sn = 4, Cn = 64;
constexpr int SCn = Sn * Cn;                // 256
constexpr int NPIX = Bn * Hn * Wn;          // 262144

// Scratch (static device arrays -- allocation-free rule)
__device__ float g_xpre[(size_t)Cn * NPIX];                 // [b][c][y][x] channel-major
__device__ __align__(16) float g_hpost[(size_t)NPIX * Sn];  // [pix][4]
__device__ __align__(16) float g_hres[(size_t)NPIX * 16];   // [pix][16] final (sinkhorn'd)

union F2U { float2 f; unsigned long long u; };

__device__ __forceinline__ unsigned long long pack2(float v) {
    F2U t; t.f = make_float2(v, v); return t.u;
}
__device__ __forceinline__ void ffma2(unsigned long long& d, unsigned long long a, unsigned long long b) {
    asm("fma.rn.f32x2 %0, %1, %2, %0;" : "+l"(d) : "l"(a), "l"(b));
}

// ---------------------------------------------------------------------------
// Kernel 1: projections + inline Sinkhorn. ONE THREAD PER PIXEL.
// x chunks staged via shared ([256][33], conflict-free), weights broadcast.
// All 24 dots in packed f32x2 registers -> no shuffles, no reductions.
// ---------------------------------------------------------------------------
constexpr int SX_STRIDE = 33;
constexpr int SX_FLOATS = 256 * SX_STRIDE;          // 8448
constexpr int SW_FLOATS = 256 * 24;                 // 6144
constexpr int PROJ_SMEM = (SX_FLOATS + SW_FLOATS) * 4;  // 58368 B

__global__ void __launch_bounds__(256) proj_kernel(
    const float* __restrict__ x,
    const float* __restrict__ w_pre, const float* __restrict__ w_post, const float* __restrict__ w_res,
    const float* __restrict__ b_pre, const float* __restrict__ b_res, const float* __restrict__ b_post,
    const float* __restrict__ alpha_pre, const float* __restrict__ alpha_res, const float* __restrict__ alpha_post,
    const float* __restrict__ rms_w)
{
    extern __shared__ __align__(16) float dsm[];
    float* s_x = dsm;                    // [256][SX_STRIDE]
    float* s_w = dsm + SX_FLOATS;        // [256 features][24 outputs]
    __shared__ float b_all[24];

    const int tid = threadIdx.x;
    {
        const int f = tid;
        const float rw = rms_w[f];
        const float apre = alpha_pre[0], ares = alpha_res[0], apost = alpha_post[0];
#pragma unroll
        for (int o = 0; o < 4; o++)  s_w[f * 24 + o]      = apre  * w_pre[o * SCn + f]  * rw;
#pragma unroll
        for (int o = 0; o < 16; o++) s_w[f * 24 + 4 + o]  = ares  * w_res[o * SCn + f]  * rw;
#pragma unroll
        for (int o = 0; o < 4; o++)  s_w[f * 24 + 20 + o] = apost * w_post[o * SCn + f] * rw;
        if (tid < 4)       b_all[tid] = b_pre[tid];
        else if (tid < 20) b_all[tid] = b_res[tid - 4];
        else if (tid < 24) b_all[tid] = b_post[tid - 20];
    }

    const size_t pixbase = (size_t)blockIdx.x * 256;
    const size_t pix = pixbase + tid;

    // ---------------- pass 1: matvec (24 outputs) + sum of squares ----------
    unsigned long long acc[12];
#pragma unroll
    for (int j = 0; j < 12; j++) acc[j] = 0ull;
    float ss = 0.f;

#pragma unroll 1
    for (int ch = 0; ch < 8; ch++) {
        __syncthreads();
#pragma unroll
        for (int k = 0; k < 32; k++) {
            const int e = tid + k * 256;
            const int p = e >> 5, f = e & 31;
            s_x[p * SX_STRIDE + f] = x[(pixbase + p) * SCn + ch * 32 + f];
        }
        __syncthreads();
#pragma unroll
        for (int f = 0; f < 32; f++) {
            const float xf = s_x[tid * SX_STRIDE + f];
            ss = fmaf(xf, xf, ss);
            const unsigned long long xx = pack2(xf);
            const ulonglong2* w2 = reinterpret_cast<const ulonglong2*>(s_w + (ch * 32 + f) * 24);
#pragma unroll
            for (int q = 0; q < 6; q++) {
                const ulonglong2 w = w2[q];
                ffma2(acc[2 * q],     xx, w.x);
                ffma2(acc[2 * q + 1], xx, w.y);
            }
        }
    }

    const float rms = rsqrtf(ss * (1.0f / 256.0f) + 1.1920929e-07f);
    float s24[24];
#pragma unroll
    for (int j = 0; j < 12; j++) {
        F2U t; t.u = acc[j];
        s24[2 * j] = t.f.x; s24[2 * j + 1] = t.f.y;
    }

    // h_pre / h_post gates
    float hp[4];
#pragma unroll
    for (int s = 0; s < 4; s++)
        hp[s] = __fdividef(1.0f, 1.0f + __expf(-(s24[s] * rms + b_all[s])));
    {
        float4 hq;
        hq.x = __fdividef(2.0f, 1.0f + __expf(-(s24[20] * rms + b_all[20])));
        hq.y = __fdividef(2.0f, 1.0f + __expf(-(s24[21] * rms + b_all[21])));
        hq.z = __fdividef(2.0f, 1.0f + __expf(-(s24[22] * rms + b_all[22])));
        hq.w = __fdividef(2.0f, 1.0f + __expf(-(s24[23] * rms + b_all[23])));
        *reinterpret_cast<float4*>(g_hpost + pix * 4) = hq;
    }

    // ---------------- inline Sinkhorn on registers ---------------------------
    {
        float v[16];
#pragma unroll
        for (int j = 0; j < 16; j++) v[j] = s24[4 + j] * rms + b_all[4 + j];
        float m = v[0];
#pragma unroll
        for (int j = 1; j < 16; j++) m = fmaxf(m, v[j]);
#pragma unroll
        for (int j = 0; j < 16; j++) v[j] = __expf(v[j] - m);
#pragma unroll 1
        for (int it = 0; it < 20; ++it) {
#pragma unroll
            for (int t = 0; t < 4; t++) {
                const float cs = v[t] + v[4 + t] + v[8 + t] + v[12 + t];
                const float inv = __fdividef(1.0f, cs + 1e-6f);
                v[t] *= inv; v[4 + t] *= inv; v[8 + t] *= inv; v[12 + t] *= inv;
            }
#pragma unroll
            for (int s = 0; s < 4; s++) {
                const float rs = v[4 * s] + v[4 * s + 1] + v[4 * s + 2] + v[4 * s + 3];
                const float inv = __fdividef(1.0f, rs + 1e-6f);
                v[4 * s] *= inv; v[4 * s + 1] *= inv; v[4 * s + 2] *= inv; v[4 * s + 3] *= inv;
            }
        }
        float4* hq = reinterpret_cast<float4*>(g_hres + pix * 16);
        hq[0] = make_float4(v[0], v[1], v[2], v[3]);
        hq[1] = make_float4(v[4], v[5], v[6], v[7]);
        hq[2] = make_float4(v[8], v[9], v[10], v[11]);
        hq[3] = make_float4(v[12], v[13], v[14], v[15]);
    }

    // ---------------- pass 2: x_pre = sum_s h_pre[s] * x[s,:] ---------------
    float xpre[64];
#pragma unroll
    for (int c = 0; c < 64; c++) xpre[c] = 0.f;

#pragma unroll 1
    for (int ch = 0; ch < 8; ch++) {
        const int s = ch >> 1, half = ch & 1;
        __syncthreads();
#pragma unroll
        for (int k = 0; k < 32; k++) {
            const int e = tid + k * 256;
            const int p = e >> 5, f = e & 31;
            s_x[p * SX_STRIDE + f] = x[(pixbase + p) * SCn + ch * 32 + f];
        }
        __syncthreads();
        const float h = hp[s];
#pragma unroll
        for (int c = 0; c < 32; c++)
            xpre[half * 32 + c] = fmaf(h, s_x[tid * SX_STRIDE + c], xpre[half * 32 + c]);
    }

    // channel-major writeout (consecutive tid -> consecutive x => coalesced)
    {
        const int b  = (int)(pix >> 14);
        const int yx = (int)(pix & 16383);
#pragma unroll
        for (int c = 0; c < 64; c++)
            g_xpre[(((size_t)b * 64 + c) << 14) + yx] = xpre[c];
    }
}

// ---------------------------------------------------------------------------
// Kernel 2: 3x3 conv (f32x2 FMA, 4px x 16ch per thread) + full epilogue:
// out = einsum(h_res, x) + h_post * layer_out
// ---------------------------------------------------------------------------
constexpr int TILE_H = 8, TILE_W = 32;
constexpr int IN_H = TILE_H + 2;                    // 10
constexpr int IN_W2 = 36;                           // padded (mult of 4) halo width
constexpr int CI_CHUNK = 16;
constexpr int SX_ELEMS = CI_CHUNK * IN_H * IN_W2;   // 5760
constexpr int SW_ELEMS = 9 * CI_CHUNK * 64;         // 9216
constexpr int SL_STRIDE = 66;
constexpr int SL_ELEMS = 256 * SL_STRIDE;           // 16896
constexpr int SMEM_FLOATS = (SX_ELEMS + SW_ELEMS) > SL_ELEMS ? (SX_ELEMS + SW_ELEMS) : SL_ELEMS;

__global__ void __launch_bounds__(256, 2) conv_kernel(
    const float* __restrict__ conv_w,
    const float* __restrict__ x,
    float* __restrict__ out)
{
    extern __shared__ __align__(16) float smem[];
    float* s_x = smem;                 // [CI_CHUNK][IN_H][IN_W2]
    float* s_w = smem + SX_ELEMS;      // [9][CI_CHUNK][64]

    const int tid = threadIdx.x;
    const int cg  = tid >> 6;          // 16-channel group 0..3
    const int r   = tid & 63;
    const int py  = r >> 3;            // 0..7
    const int x0  = (r & 7) * 4;       // 0,4,...,28
    const int b   = blockIdx.z;
    const int gy0 = blockIdx.y * TILE_H;
    const int gx0 = blockIdx.x * TILE_W;

    unsigned long long acc[4][8];      // 4 pixels x 16 channels (8 f32x2)
#pragma unroll
    for (int p = 0; p < 4; p++)
#pragma unroll
        for (int j = 0; j < 8; j++) acc[p][j] = 0ull;

#pragma unroll 1
    for (int chunk = 0; chunk < Cn / CI_CHUNK; ++chunk) {
        __syncthreads();
        for (int e = tid; e < SX_ELEMS; e += 256) {
            const int ci  = e / (IN_H * IN_W2);
            const int rem = e - ci * (IN_H * IN_W2);
            const int iy = rem / IN_W2, ix = rem - iy * IN_W2;
            const int gy = gy0 + iy - 1, gx = gx0 + ix - 1;
            float v = 0.f;
            if ((unsigned)gy < 128u && (unsigned)gx < 128u)
                v = g_xpre[(((size_t)b * 64 + chunk * CI_CHUNK + ci) * 128 + gy) * 128 + gx];
            s_x[e] = v;
        }
        for (int e = tid; e < SW_ELEMS; e += 256) {
            const int co = e & 63;
            const int ci = (e >> 6) & (CI_CHUNK - 1);
            const int kk = e >> 10;
            s_w[e] = conv_w[((size_t)kk * 64 + chunk * CI_CHUNK + ci) * 64 + co];
        }
        __syncthreads();

#pragma unroll 1
        for (int ci = 0; ci < CI_CHUNK; ++ci) {
#pragma unroll
            for (int ky = 0; ky < 3; ++ky) {
                const float* xr = s_x + (ci * IN_H + py + ky) * IN_W2 + x0;
                const float4 a0 = *reinterpret_cast<const float4*>(xr);
                const float2 a1 = *reinterpret_cast<const float2*>(xr + 4);
                const float xa[6] = {a0.x, a0.y, a0.z, a0.w, a1.x, a1.y};
#pragma unroll
                for (int kx = 0; kx < 3; ++kx) {
                    const ulonglong2* wr = reinterpret_cast<const ulonglong2*>(
                        s_w + ((ky * 3 + kx) * CI_CHUNK + ci) * 64 + cg * 16);
                    const ulonglong2 wA = wr[0], wB = wr[1];
#pragma unroll
                    for (int p = 0; p < 4; ++p) {
                        const unsigned long long xx = pack2(xa[p + kx]);
                        ffma2(acc[p][0], xx, wA.x);
                        ffma2(acc[p][1], xx, wA.y);
                        ffma2(acc[p][2], xx, wB.x);
                        ffma2(acc[p][3], xx, wB.y);
                        ffma2(acc[p][4], xx, wr[2].x);
                        ffma2(acc[p][5], xx, wr[2].y);
                        ffma2(acc[p][6], xx, wr[3].x);
                        ffma2(acc[p][7], xx, wr[3].y);
                    }
                }
            }
        }
    }

    // stage layer_out in shared: s_l[pixel_local][channel]
    __syncthreads();
    float* s_l = smem;   // [256][SL_STRIDE]
#pragma unroll
    for (int p = 0; p < 4; ++p) {
        float* dst = s_l + (py * 32 + x0 + p) * SL_STRIDE + cg * 16;
#pragma unroll
        for (int j = 0; j < 8; ++j) {
            F2U t; t.u = acc[p][j];
            *reinterpret_cast<float2*>(dst + 2 * j) = t.f;
        }
    }
    __syncthreads();

    // epilogue: out = einsum(h_res, x) + h_post * layer_out
    const int lane = tid & 31, wrp = tid >> 5;
    const int gy = gy0 + wrp;
    for (int pp = 0; pp < 32; ++pp) {
        const size_t pix = ((size_t)b * 128 + gy) * 128 + (gx0 + pp);
        const float* xp = x + pix * SCn;
        const float4* hq = reinterpret_cast<const float4*>(g_hres + pix * 16);
        const float4 h0 = hq[0], h1 = hq[1], h2 = hq[2], h3 = hq[3];
        const float4 hpst = *reinterpret_cast<const float4*>(g_hpost + pix * 4);
        const float* lrow = s_l + (wrp * 32 + pp) * SL_STRIDE;
        float* op = out + pix * SCn;
#pragma unroll
        for (int p2 = 0; p2 < 2; ++p2) {
            const int c = p2 * 32 + lane;
            const float l  = lrow[c];
            const float t0 = xp[c];
            const float t1 = xp[64 + c];
            const float t2 = xp[128 + c];
            const float t3 = xp[192 + c];
            op[c]       = h0.x * t0 + h0.y * t1 + h0.z * t2 + h0.w * t3 + hpst.x * l;
            op[64 + c]  = h1.x * t0 + h1.y * t1 + h1.z * t2 + h1.w * t3 + hpst.y * l;
            op[128 + c] = h2.x * t0 + h2.y * t1 + h2.z * t2 + h2.w * t3 + hpst.z * l;
            op[192 + c] = h3.x * t0 + h3.y * t1 + h3.z * t2 + h3.w * t3 + hpst.w * l;
        }
    }
}

// ---------------------------------------------------------------------------
extern "C" void kernel_launch(void* const* d_in, const int* in_sizes, int n_in,
                              void* d_out, int out_size)
{
    const float* x       = (const float*)d_in[0];
    const float* w_pre   = (const float*)d_in[1];
    const float* w_post  = (const float*)d_in[2];
    const float* w_res   = (const float*)d_in[3];
    const float* b_pre   = (const float*)d_in[4];
    const float* b_res   = (const float*)d_in[5];
    const float* b_post  = (const float*)d_in[6];
    const float* a_pre   = (const float*)d_in[7];
    const float* a_res   = (const float*)d_in[8];
    const float* a_post  = (const float*)d_in[9];
    const float* rms_w   = (const float*)d_in[10];
    const float* conv_w  = (const float*)d_in[11];
    float* out = (float*)d_out;

    cudaFuncSetAttribute(proj_kernel, cudaFuncAttributeMaxDynamicSharedMemorySize, PROJ_SMEM);
    proj_kernel<<<NPIX / 256, 256, PROJ_SMEM>>>(x, w_pre, w_post, w_res,
                                                b_pre, b_res, b_post,
                                                a_pre, a_res, a_post, rms_w);

    cudaFuncSetAttribute(conv_kernel, cudaFuncAttributeMaxDynamicSharedMemorySize,
                         SMEM_FLOATS * (int)sizeof(float));
    conv_kernel<<<dim3(Wn / TILE_W, Hn / TILE_H, Bn), 256, SMEM_FLOATS * sizeof(float)>>>(
        conv_w, x, out);
}

// round 5
// speedup vs baseline: 1.6842x; 1.2260x over previous
#include <cuda_runtime.h>
#include <cuda_bf16.h>
#include <cstdint>

#define FULL 0xffffffffu

constexpr int Bn = 16, Hn = 128, Wn = 128, Sn = 4, Cn = 64;
constexpr int SCn = Sn * Cn;                // 256
constexpr int NPIX = Bn * Hn * Wn;          // 262144

// Scratch (static device arrays -- allocation-free rule)
__device__ __nv_bfloat16 g_xpb[(size_t)NPIX * 128];        // [pix][hi(64)|lo(64)] bf16
__device__ __align__(16) float g_hpost[(size_t)NPIX * Sn]; // [pix][4]
__device__ __align__(16) float g_hpre[(size_t)NPIX * Sn];  // [pix][4]
__device__ __align__(16) float g_hres[(size_t)NPIX * 16];  // [pix][16] (sinkhorn'd)
__device__ __nv_bfloat16 g_wb[6 * 64 * 384];               // [ky][pass][co][k=384] row-major

union F2U { float2 f; unsigned long long u; };

__device__ __forceinline__ unsigned long long pack2(float v) {
    F2U t; t.f = make_float2(v, v); return t.u;
}
__device__ __forceinline__ void ffma2(unsigned long long& d, unsigned long long a, unsigned long long b) {
    asm("fma.rn.f32x2 %0, %1, %2, %0;" : "+l"(d) : "l"(a), "l"(b));
}
__device__ __forceinline__ uint32_t smem_u32(const void* p) {
    uint32_t a;
    asm("{ .reg .u64 t; cvta.to.shared.u64 t, %1; cvt.u32.u64 %0, t; }" : "=r"(a) : "l"(p));
    return a;
}
__device__ __forceinline__ void ldsm4(uint32_t& r0, uint32_t& r1, uint32_t& r2, uint32_t& r3, uint32_t addr) {
    asm volatile("ldmatrix.sync.aligned.m8n8.x4.shared.b16 {%0,%1,%2,%3}, [%4];"
                 : "=r"(r0), "=r"(r1), "=r"(r2), "=r"(r3) : "r"(addr));
}
__device__ __forceinline__ void mma16816(float* d, uint32_t a0, uint32_t a1, uint32_t a2, uint32_t a3,
                                         uint32_t b0, uint32_t b1) {
    asm volatile("mma.sync.aligned.m16n8k16.row.col.f32.bf16.bf16.f32 "
                 "{%0,%1,%2,%3}, {%4,%5,%6,%7}, {%8,%9}, {%0,%1,%2,%3};"
                 : "+f"(d[0]), "+f"(d[1]), "+f"(d[2]), "+f"(d[3])
                 : "r"(a0), "r"(a1), "r"(a2), "r"(a3), "r"(b0), "r"(b1));
}

// ---------------------------------------------------------------------------
// Kernel 0: weight prep. conv_w HWIO fp32 -> g_wb[ky][pass][co][k], k=(kx,part,ci).
// pass0 = hi duplicated over both part slots, pass1 = lo duplicated.
// ---------------------------------------------------------------------------
__global__ void wprep_kernel(const float* __restrict__ conv_w)
{
    const int e = blockIdx.x * 256 + threadIdx.x;      // 0 .. 6*64*384-1
    if (e >= 6 * 64 * 384) return;
    const int tile = e / (64 * 384);                   // ky*2 + pass
    const int rem = e - tile * (64 * 384);
    const int co = rem / 384, k = rem - co * 384;
    const int ky = tile >> 1, pass = tile & 1;
    const int kx = k >> 7, ci = k & 63;
    const float w = conv_w[((size_t)(ky * 3 + kx) * 64 + ci) * 64 + co];
    const __nv_bfloat16 hi = __float2bfloat16(w);
    __nv_bfloat16 v = hi;
    if (pass) v = __float2bfloat16(w - __bfloat162float(hi));
    g_wb[e] = v;
}

// ---------------------------------------------------------------------------
// Kernel 1: projections + inline Sinkhorn. ONE THREAD PER PIXEL.
// Double-buffered register prefetch of x chunks.
// ---------------------------------------------------------------------------
constexpr int SX_STRIDE = 33;
constexpr int SX_FLOATS = 256 * SX_STRIDE;              // 8448
constexpr int SW_FLOATS = 256 * 24;                     // 6144
constexpr int PROJ_SMEM = (SX_FLOATS + SW_FLOATS) * 4;  // 58368 B

__global__ void __launch_bounds__(256) proj_kernel(
    const float* __restrict__ x,
    const float* __restrict__ w_pre, const float* __restrict__ w_post, const float* __restrict__ w_res,
    const float* __restrict__ b_pre, const float* __restrict__ b_res, const float* __restrict__ b_post,
    const float* __restrict__ alpha_pre, const float* __restrict__ alpha_res, const float* __restrict__ alpha_post,
    const float* __restrict__ rms_w)
{
    extern __shared__ __align__(16) float dsm[];
    float* s_x = dsm;                    // [256][SX_STRIDE]
    float* s_w = dsm + SX_FLOATS;        // [256 features][24 outputs]
    __shared__ float b_all[24];

    const int tid = threadIdx.x;
    {
        const int f = tid;
        const float rw = rms_w[f];
        const float apre = alpha_pre[0], ares = alpha_res[0], apost = alpha_post[0];
#pragma unroll
        for (int o = 0; o < 4; o++)  s_w[f * 24 + o]      = apre  * w_pre[o * SCn + f]  * rw;
#pragma unroll
        for (int o = 0; o < 16; o++) s_w[f * 24 + 4 + o]  = ares  * w_res[o * SCn + f]  * rw;
#pragma unroll
        for (int o = 0; o < 4; o++)  s_w[f * 24 + 20 + o] = apost * w_post[o * SCn + f] * rw;
        if (tid < 4)       b_all[tid] = b_pre[tid];
        else if (tid < 20) b_all[tid] = b_res[tid - 4];
        else if (tid < 24) b_all[tid] = b_post[tid - 20];
    }

    const size_t pixbase = (size_t)blockIdx.x * 256;
    const size_t pix = pixbase + tid;
    const float* xb = x + pixbase * SCn;

    unsigned long long acc[12];
#pragma unroll
    for (int j = 0; j < 12; j++) acc[j] = 0ull;
    float ss = 0.f;

    float4 rr[8];
#pragma unroll
    for (int k = 0; k < 8; k++) {
        const int e4 = tid + k * 256;
        const int p = e4 >> 3, f4 = (e4 & 7) * 4;
        rr[k] = *reinterpret_cast<const float4*>(&xb[p * SCn + 0 * 32 + f4]);
    }

#pragma unroll 1
    for (int ch = 0; ch < 8; ch++) {
        __syncthreads();
#pragma unroll
        for (int k = 0; k < 8; k++) {
            const int e4 = tid + k * 256;
            const int p = e4 >> 3, f4 = (e4 & 7) * 4;
            s_x[p * SX_STRIDE + f4 + 0] = rr[k].x;
            s_x[p * SX_STRIDE + f4 + 1] = rr[k].y;
            s_x[p * SX_STRIDE + f4 + 2] = rr[k].z;
            s_x[p * SX_STRIDE + f4 + 3] = rr[k].w;
        }
        __syncthreads();
        if (ch < 7) {
#pragma unroll
            for (int k = 0; k < 8; k++) {
                const int e4 = tid + k * 256;
                const int p = e4 >> 3, f4 = (e4 & 7) * 4;
                rr[k] = *reinterpret_cast<const float4*>(&xb[p * SCn + (ch + 1) * 32 + f4]);
            }
        }
#pragma unroll
        for (int f = 0; f < 32; f++) {
            const float xf = s_x[tid * SX_STRIDE + f];
            ss = fmaf(xf, xf, ss);
            const unsigned long long xx = pack2(xf);
            const ulonglong2* w2 = reinterpret_cast<const ulonglong2*>(s_w + (ch * 32 + f) * 24);
#pragma unroll
            for (int q = 0; q < 6; q++) {
                const ulonglong2 w = w2[q];
                ffma2(acc[2 * q],     xx, w.x);
                ffma2(acc[2 * q + 1], xx, w.y);
            }
        }
    }

    const float rms = rsqrtf(ss * (1.0f / 256.0f) + 1.1920929e-07f);
    float s24[24];
#pragma unroll
    for (int j = 0; j < 12; j++) {
        F2U t; t.u = acc[j];
        s24[2 * j] = t.f.x; s24[2 * j + 1] = t.f.y;
    }

    {
        float4 hq;
        hq.x = __fdividef(1.0f, 1.0f + __expf(-(s24[0] * rms + b_all[0])));
        hq.y = __fdividef(1.0f, 1.0f + __expf(-(s24[1] * rms + b_all[1])));
        hq.z = __fdividef(1.0f, 1.0f + __expf(-(s24[2] * rms + b_all[2])));
        hq.w = __fdividef(1.0f, 1.0f + __expf(-(s24[3] * rms + b_all[3])));
        *reinterpret_cast<float4*>(g_hpre + pix * 4) = hq;
    }
    {
        float4 hq;
        hq.x = __fdividef(2.0f, 1.0f + __expf(-(s24[20] * rms + b_all[20])));
        hq.y = __fdividef(2.0f, 1.0f + __expf(-(s24[21] * rms + b_all[21])));
        hq.z = __fdividef(2.0f, 1.0f + __expf(-(s24[22] * rms + b_all[22])));
        hq.w = __fdividef(2.0f, 1.0f + __expf(-(s24[23] * rms + b_all[23])));
        *reinterpret_cast<float4*>(g_hpost + pix * 4) = hq;
    }

    // ---------------- inline Sinkhorn on registers ---------------------------
    {
        float v[16];
#pragma unroll
        for (int j = 0; j < 16; j++) v[j] = s24[4 + j] * rms + b_all[4 + j];
        float m = v[0];
#pragma unroll
        for (int j = 1; j < 16; j++) m = fmaxf(m, v[j]);
#pragma unroll
        for (int j = 0; j < 16; j++) v[j] = __expf(v[j] - m);
#pragma unroll 1
        for (int it = 0; it < 20; ++it) {
#pragma unroll
            for (int t = 0; t < 4; t++) {
                const float cs = v[t] + v[4 + t] + v[8 + t] + v[12 + t];
                const float inv = __fdividef(1.0f, cs + 1e-6f);
                v[t] *= inv; v[4 + t] *= inv; v[8 + t] *= inv; v[12 + t] *= inv;
            }
#pragma unroll
            for (int s = 0; s < 4; s++) {
                const float rs = v[4 * s] + v[4 * s + 1] + v[4 * s + 2] + v[4 * s + 3];
                const float inv = __fdividef(1.0f, rs + 1e-6f);
                v[4 * s] *= inv; v[4 * s + 1] *= inv; v[4 * s + 2] *= inv; v[4 * s + 3] *= inv;
            }
        }
        float4* hq = reinterpret_cast<float4*>(g_hres + pix * 16);
        hq[0] = make_float4(v[0], v[1], v[2], v[3]);
        hq[1] = make_float4(v[4], v[5], v[6], v[7]);
        hq[2] = make_float4(v[8], v[9], v[10], v[11]);
        hq[3] = make_float4(v[12], v[13], v[14], v[15]);
    }
}

// ---------------------------------------------------------------------------
// Kernel 2: x_pre = sum_s h_pre[s]*x[s,:], bf16 hi/lo output. 64 px / block.
// ---------------------------------------------------------------------------
constexpr int XP_STRIDE = 261;
constexpr int XPRE_SMEM = 64 * XP_STRIDE * 4;   // 66816 B

__global__ void __launch_bounds__(256) xpre_kernel(const float* __restrict__ x)
{
    extern __shared__ __align__(16) float sx[];
    __shared__ float s_hp[64][4];

    const int tid = threadIdx.x;
    const size_t pixbase = (size_t)blockIdx.x * 64;

    // stage x[64px][256f] (coalesced float4)
#pragma unroll
    for (int k = 0; k < 16; k++) {
        const int e4 = tid + k * 256;
        const int p = e4 >> 6, f4 = (e4 & 63) * 4;
        const float4 v = *reinterpret_cast<const float4*>(&x[(pixbase + p) * SCn + f4]);
        sx[p * XP_STRIDE + f4 + 0] = v.x;
        sx[p * XP_STRIDE + f4 + 1] = v.y;
        sx[p * XP_STRIDE + f4 + 2] = v.z;
        sx[p * XP_STRIDE + f4 + 3] = v.w;
    }
    if (tid < 64) {
        const float4 h = *reinterpret_cast<const float4*>(g_hpre + (pixbase + tid) * 4);
        s_hp[tid][0] = h.x; s_hp[tid][1] = h.y; s_hp[tid][2] = h.z; s_hp[tid][3] = h.w;
    }
    __syncthreads();

    const int p = tid & 63, ch2 = tid >> 6;     // 16 channels per thread
    const float h0 = s_hp[p][0], h1 = s_hp[p][1], h2 = s_hp[p][2], h3 = s_hp[p][3];
    const float* row = sx + p * XP_STRIDE + ch2 * 16;

    uint32_t uhi[8], ulo[8];
#pragma unroll
    for (int j2 = 0; j2 < 8; j2++) {
        uint32_t h_pack = 0, l_pack = 0;
#pragma unroll
        for (int half = 0; half < 2; half++) {
            const int c = j2 * 2 + half;
            const float v = h0 * row[c] + h1 * row[64 + c] + h2 * row[128 + c] + h3 * row[192 + c];
            const __nv_bfloat16 hi = __float2bfloat16(v);
            const __nv_bfloat16 lo = __float2bfloat16(v - __bfloat162float(hi));
            h_pack |= (uint32_t)__bfloat16_as_ushort(hi) << (16 * half);
            l_pack |= (uint32_t)__bfloat16_as_ushort(lo) << (16 * half);
        }
        uhi[j2] = h_pack; ulo[j2] = l_pack;
    }
    uint4* dst = reinterpret_cast<uint4*>(g_xpb + (pixbase + p) * 128);
    dst[ch2 * 2 + 0] = make_uint4(uhi[0], uhi[1], uhi[2], uhi[3]);
    dst[ch2 * 2 + 1] = make_uint4(uhi[4], uhi[5], uhi[6], uhi[7]);
    dst[8 + ch2 * 2 + 0] = make_uint4(ulo[0], ulo[1], ulo[2], ulo[3]);
    dst[8 + ch2 * 2 + 1] = make_uint4(ulo[4], ulo[5], ulo[6], ulo[7]);
}

// ---------------------------------------------------------------------------
// Kernel 3: conv via mma.sync bf16 (hi/lo in K) + epilogue.
// One CTA per image row: D[128px][64co] = sum_ky A_ky[128][384] * B_ky^T (2 passes).
// ---------------------------------------------------------------------------
constexpr int A_STRIDE = 392;              // bf16 units (odd # of 16B -> ldmatrix conflict-free)
constexpr int ASB = A_STRIDE * 2;          // 784 bytes
constexpr int A_BYTES = 128 * ASB;         // 100352
constexpr int B_BYTES = 128 * ASB;         // 2 passes x 64 rows
constexpr int CONV_SMEM = A_BYTES + B_BYTES;   // 200704

__global__ void __launch_bounds__(256, 1) conv_kernel(const float* __restrict__ x,
                                                      float* __restrict__ out)
{
    extern __shared__ __align__(16) char smem[];
    char* s_a = smem;
    char* s_b = smem + A_BYTES;
    const uint32_t sa = smem_u32(smem);
    const uint32_t sb = sa + A_BYTES;

    const int tid = threadIdx.x;
    const int wid = tid >> 5, lane = tid & 31;
    const int y = blockIdx.x, b = blockIdx.y;

    float d[8][4];
#pragma unroll
    for (int t = 0; t < 8; t++)
#pragma unroll
        for (int j = 0; j < 4; j++) d[t][j] = 0.f;

    const uint32_t a_off = sa + (uint32_t)(16 * wid + (lane & 15)) * ASB + (uint32_t)((lane >> 4) << 4);
    uint32_t b_off[4];
#pragma unroll
    for (int t = 0; t < 4; t++)
        b_off[t] = sb + (uint32_t)(16 * t + (lane & 7) + ((lane >> 4) << 3)) * ASB
                      + (uint32_t)(((lane >> 3) & 1) << 4);

#pragma unroll 1
    for (int ky = 0; ky < 3; ++ky) {
        const int y2 = y + ky - 1;
        if ((unsigned)y2 >= 128u) continue;
        __syncthreads();   // prior ldmatrix reads complete before restage

        // ---- stage A_ky: im2col overlap-copy, row-major stride 392 bf16 ----
        {
            const uint4* src = reinterpret_cast<const uint4*>(
                g_xpb + ((size_t)(b * 128 + y2) * 128) * 128);
#pragma unroll
            for (int i = 0; i < 8; i++) {
                const int u = tid + i * 256;
                const int xs = u >> 4, q = u & 15;
                const uint4 v = src[u];
#pragma unroll
                for (int kx = 0; kx < 3; kx++) {
                    const int m = xs + 1 - kx;
                    if ((unsigned)m < 128u)
                        *reinterpret_cast<uint4*>(s_a + m * ASB + kx * 256 + q * 16) = v;
                }
            }
            if (tid < 32) {
                const int slot = tid >> 4, q = tid & 15;
                const int m = slot ? 127 : 0;
                *reinterpret_cast<uint4*>(s_a + m * ASB + (slot ? 512 : 0) + q * 16) =
                    make_uint4(0, 0, 0, 0);
            }
        }
        // ---- stage B (both passes): [row=pass*64+co][384] ----
        {
            const uint4* wsrc = reinterpret_cast<const uint4*>(g_wb + (size_t)ky * 2 * 64 * 384);
#pragma unroll
            for (int i = 0; i < 24; i++) {
                const int e = tid + i * 256;
                const int row = e / 48, c16 = e - row * 48;
                *reinterpret_cast<uint4*>(s_b + row * ASB + c16 * 16) = wsrc[e];
            }
        }
        __syncthreads();

        // ---- MMA mainloop ----
#pragma unroll 1
        for (int pass = 0; pass < 2; pass++) {
            const uint32_t bp = (uint32_t)pass * 64u * ASB;
#pragma unroll 4
            for (int kk = 0; kk < 24; kk++) {
                uint32_t a0, a1, a2, a3;
                ldsm4(a0, a1, a2, a3, a_off + kk * 32);
#pragma unroll
                for (int t = 0; t < 4; t++) {
                    uint32_t b0, b1, b2, b3;
                    ldsm4(b0, b1, b2, b3, b_off[t] + bp + kk * 32);
                    mma16816(d[2 * t],     a0, a1, a2, a3, b0, b1);
                    mma16816(d[2 * t + 1], a0, a1, a2, a3, b2, b3);
                }
            }
        }
    }

    __syncthreads();
    // ---- write layer_out to smem [128][65] ----
    float* s_l = reinterpret_cast<float*>(smem);
    {
        const int gid = lane >> 2, tig = lane & 3;
#pragma unroll
        for (int t = 0; t < 4; t++)
#pragma unroll
            for (int h = 0; h < 2; h++) {
                const int nt = 2 * t + h, nb = 16 * t + 8 * h;
                s_l[(16 * wid + gid) * 65 + nb + 2 * tig]     = d[nt][0];
                s_l[(16 * wid + gid) * 65 + nb + 2 * tig + 1] = d[nt][1];
                s_l[(16 * wid + gid + 8) * 65 + nb + 2 * tig]     = d[nt][2];
                s_l[(16 * wid + gid + 8) * 65 + nb + 2 * tig + 1] = d[nt][3];
            }
    }
    __syncthreads();

    // ---- epilogue: out = einsum(h_res, x) + h_post * layer_out ----
    const size_t rowpix = ((size_t)b * 128 + y) * 128;
#pragma unroll 1
    for (int pp = 0; pp < 16; ++pp) {
        const int m = wid * 16 + pp;
        const size_t pix = rowpix + m;
        const float* xp = x + pix * SCn;
        const float4* hq = reinterpret_cast<const float4*>(g_hres + pix * 16);
        const float4 h0 = hq[0], h1 = hq[1], h2 = hq[2], h3 = hq[3];
        const float4 hpst = *reinterpret_cast<const float4*>(g_hpost + pix * 4);
        const float* lrow = s_l + m * 65;
        float* op = out + pix * SCn;
#pragma unroll
        for (int p2 = 0; p2 < 2; ++p2) {
            const int c = p2 * 32 + lane;
            const float l  = lrow[c];
            const float t0 = xp[c];
            const float t1 = xp[64 + c];
            const float t2 = xp[128 + c];
            const float t3 = xp[192 + c];
            op[c]       = h0.x * t0 + h0.y * t1 + h0.z * t2 + h0.w * t3 + hpst.x * l;
            op[64 + c]  = h1.x * t0 + h1.y * t1 + h1.z * t2 + h1.w * t3 + hpst.y * l;
            op[128 + c] = h2.x * t0 + h2.y * t1 + h2.z * t2 + h2.w * t3 + hpst.z * l;
            op[192 + c] = h3.x * t0 + h3.y * t1 + h3.z * t2 + h3.w * t3 + hpst.w * l;
        }
    }
}

// ---------------------------------------------------------------------------
extern "C" void kernel_launch(void* const* d_in, const int* in_sizes, int n_in,
                              void* d_out, int out_size)
{
    const float* x       = (const float*)d_in[0];
    const float* w_pre   = (const float*)d_in[1];
    const float* w_post  = (const float*)d_in[2];
    const float* w_res   = (const float*)d_in[3];
    const float* b_pre   = (const float*)d_in[4];
    const float* b_res   = (const float*)d_in[5];
    const float* b_post  = (const float*)d_in[6];
    const float* a_pre   = (const float*)d_in[7];
    const float* a_res   = (const float*)d_in[8];
    const float* a_post  = (const float*)d_in[9];
    const float* rms_w   = (const float*)d_in[10];
    const float* conv_w  = (const float*)d_in[11];
    float* out = (float*)d_out;

    wprep_kernel<<<(6 * 64 * 384 + 255) / 256, 256>>>(conv_w);

    cudaFuncSetAttribute(proj_kernel, cudaFuncAttributeMaxDynamicSharedMemorySize, PROJ_SMEM);
    proj_kernel<<<NPIX / 256, 256, PROJ_SMEM>>>(x, w_pre, w_post, w_res,
                                                b_pre, b_res, b_post,
                                                a_pre, a_res, a_post, rms_w);

    cudaFuncSetAttribute(xpre_kernel, cudaFuncAttributeMaxDynamicSharedMemorySize, XPRE_SMEM);
    xpre_kernel<<<NPIX / 64, 256, XPRE_SMEM>>>(x);

    cudaFuncSetAttribute(conv_kernel, cudaFuncAttributeMaxDynamicSharedMemorySize, CONV_SMEM);
    conv_kernel<<<dim3(Hn, Bn), 256, CONV_SMEM>>>(x, out);
}

// round 6
// speedup vs baseline: 1.7078x; 1.0141x over previous
#include <cuda_runtime.h>
#include <cuda_bf16.h>
#include <cstdint>

#define FULL 0xffffffffu

constexpr int Bn = 16, Hn = 128, Wn = 128, Sn = 4, Cn = 64;
constexpr int SCn = Sn * Cn;                // 256
constexpr int NPIX = Bn * Hn * Wn;          // 262144

// Scratch (static device arrays -- allocation-free rule)
__device__ __nv_bfloat16 g_xpb[(size_t)NPIX * 128];        // [pix][hi(64)|lo(64)] bf16
__device__ __align__(16) float g_hpost[(size_t)NPIX * Sn]; // [pix][4]
__device__ __align__(16) float g_hpre[(size_t)NPIX * Sn];  // [pix][4]
__device__ __align__(16) float g_hres[(size_t)NPIX * 16];  // [pix][16] (sinkhorn'd)
__device__ __nv_bfloat16 g_wb[6 * 64 * 384];               // [ky][pass][co][k=384] row-major

union F2U { float2 f; unsigned long long u; };

__device__ __forceinline__ unsigned long long pack2(float v) {
    F2U t; t.f = make_float2(v, v); return t.u;
}
__device__ __forceinline__ void ffma2(unsigned long long& d, unsigned long long a, unsigned long long b) {
    asm("fma.rn.f32x2 %0, %1, %2, %0;" : "+l"(d) : "l"(a), "l"(b));
}
__device__ __forceinline__ uint32_t smem_u32(const void* p) {
    uint32_t a;
    asm("{ .reg .u64 t; cvta.to.shared.u64 t, %1; cvt.u32.u64 %0, t; }" : "=r"(a) : "l"(p));
    return a;
}
__device__ __forceinline__ void ldsm4(uint32_t& r0, uint32_t& r1, uint32_t& r2, uint32_t& r3, uint32_t addr) {
    asm volatile("ldmatrix.sync.aligned.m8n8.x4.shared.b16 {%0,%1,%2,%3}, [%4];"
                 : "=r"(r0), "=r"(r1), "=r"(r2), "=r"(r3) : "r"(addr));
}
__device__ __forceinline__ void mma16816(float* d, uint32_t a0, uint32_t a1, uint32_t a2, uint32_t a3,
                                         uint32_t b0, uint32_t b1) {
    asm volatile("mma.sync.aligned.m16n8k16.row.col.f32.bf16.bf16.f32 "
                 "{%0,%1,%2,%3}, {%4,%5,%6,%7}, {%8,%9}, {%0,%1,%2,%3};"
                 : "+f"(d[0]), "+f"(d[1]), "+f"(d[2]), "+f"(d[3])
                 : "r"(a0), "r"(a1), "r"(a2), "r"(a3), "r"(b0), "r"(b1));
}
__device__ __forceinline__ void cp16(uint32_t smaddr, const void* g) {
    asm volatile("cp.async.cg.shared.global [%0], [%1], 16;" :: "r"(smaddr), "l"(g));
}
#define CP_COMMIT() asm volatile("cp.async.commit_group;" ::: "memory")
#define CP_WAIT0()  asm volatile("cp.async.wait_group 0;" ::: "memory")

// ---------------------------------------------------------------------------
// Kernel 0: weight prep. conv_w HWIO fp32 -> g_wb[ky][pass][co][k], k=(kx,part,ci).
// pass0 = hi duplicated over both part slots, pass1 = lo duplicated.
// ---------------------------------------------------------------------------
__global__ void wprep_kernel(const float* __restrict__ conv_w)
{
    const int e = blockIdx.x * 256 + threadIdx.x;      // 0 .. 6*64*384-1
    if (e >= 6 * 64 * 384) return;
    const int tile = e / (64 * 384);                   // ky*2 + pass
    const int rem = e - tile * (64 * 384);
    const int co = rem / 384, k = rem - co * 384;
    const int ky = tile >> 1, pass = tile & 1;
    const int kx = k >> 7, ci = k & 63;
    const float w = conv_w[((size_t)(ky * 3 + kx) * 64 + ci) * 64 + co];
    const __nv_bfloat16 hi = __float2bfloat16(w);
    __nv_bfloat16 v = hi;
    if (pass) v = __float2bfloat16(w - __bfloat162float(hi));
    g_wb[e] = v;
}

// ---------------------------------------------------------------------------
// Kernel 1: projections + inline Sinkhorn. ONE THREAD PER PIXEL. (unchanged)
// ---------------------------------------------------------------------------
constexpr int SX_STRIDE = 33;
constexpr int SX_FLOATS = 256 * SX_STRIDE;              // 8448
constexpr int SW_FLOATS = 256 * 24;                     // 6144
constexpr int PROJ_SMEM = (SX_FLOATS + SW_FLOATS) * 4;  // 58368 B

__global__ void __launch_bounds__(256) proj_kernel(
    const float* __restrict__ x,
    const float* __restrict__ w_pre, const float* __restrict__ w_post, const float* __restrict__ w_res,
    const float* __restrict__ b_pre, const float* __restrict__ b_res, const float* __restrict__ b_post,
    const float* __restrict__ alpha_pre, const float* __restrict__ alpha_res, const float* __restrict__ alpha_post,
    const float* __restrict__ rms_w)
{
    extern __shared__ __align__(16) float dsm[];
    float* s_x = dsm;                    // [256][SX_STRIDE]
    float* s_w = dsm + SX_FLOATS;        // [256 features][24 outputs]
    __shared__ float b_all[24];

    const int tid = threadIdx.x;
    {
        const int f = tid;
        const float rw = rms_w[f];
        const float apre = alpha_pre[0], ares = alpha_res[0], apost = alpha_post[0];
#pragma unroll
        for (int o = 0; o < 4; o++)  s_w[f * 24 + o]      = apre  * w_pre[o * SCn + f]  * rw;
#pragma unroll
        for (int o = 0; o < 16; o++) s_w[f * 24 + 4 + o]  = ares  * w_res[o * SCn + f]  * rw;
#pragma unroll
        for (int o = 0; o < 4; o++)  s_w[f * 24 + 20 + o] = apost * w_post[o * SCn + f] * rw;
        if (tid < 4)       b_all[tid] = b_pre[tid];
        else if (tid < 20) b_all[tid] = b_res[tid - 4];
        else if (tid < 24) b_all[tid] = b_post[tid - 20];
    }

    const size_t pixbase = (size_t)blockIdx.x * 256;
    const size_t pix = pixbase + tid;
    const float* xb = x + pixbase * SCn;

    unsigned long long acc[12];
#pragma unroll
    for (int j = 0; j < 12; j++) acc[j] = 0ull;
    float ss = 0.f;

    float4 rr[8];
#pragma unroll
    for (int k = 0; k < 8; k++) {
        const int e4 = tid + k * 256;
        const int p = e4 >> 3, f4 = (e4 & 7) * 4;
        rr[k] = *reinterpret_cast<const float4*>(&xb[p * SCn + 0 * 32 + f4]);
    }

#pragma unroll 1
    for (int ch = 0; ch < 8; ch++) {
        __syncthreads();
#pragma unroll
        for (int k = 0; k < 8; k++) {
            const int e4 = tid + k * 256;
            const int p = e4 >> 3, f4 = (e4 & 7) * 4;
            s_x[p * SX_STRIDE + f4 + 0] = rr[k].x;
            s_x[p * SX_STRIDE + f4 + 1] = rr[k].y;
            s_x[p * SX_STRIDE + f4 + 2] = rr[k].z;
            s_x[p * SX_STRIDE + f4 + 3] = rr[k].w;
        }
        __syncthreads();
        if (ch < 7) {
#pragma unroll
            for (int k = 0; k < 8; k++) {
                const int e4 = tid + k * 256;
                const int p = e4 >> 3, f4 = (e4 & 7) * 4;
                rr[k] = *reinterpret_cast<const float4*>(&xb[p * SCn + (ch + 1) * 32 + f4]);
            }
        }
#pragma unroll
        for (int f = 0; f < 32; f++) {
            const float xf = s_x[tid * SX_STRIDE + f];
            ss = fmaf(xf, xf, ss);
            const unsigned long long xx = pack2(xf);
            const ulonglong2* w2 = reinterpret_cast<const ulonglong2*>(s_w + (ch * 32 + f) * 24);
#pragma unroll
            for (int q = 0; q < 6; q++) {
                const ulonglong2 w = w2[q];
                ffma2(acc[2 * q],     xx, w.x);
                ffma2(acc[2 * q + 1], xx, w.y);
            }
        }
    }

    const float rms = rsqrtf(ss * (1.0f / 256.0f) + 1.1920929e-07f);
    float s24[24];
#pragma unroll
    for (int j = 0; j < 12; j++) {
        F2U t; t.u = acc[j];
        s24[2 * j] = t.f.x; s24[2 * j + 1] = t.f.y;
    }

    {
        float4 hq;
        hq.x = __fdividef(1.0f, 1.0f + __expf(-(s24[0] * rms + b_all[0])));
        hq.y = __fdividef(1.0f, 1.0f + __expf(-(s24[1] * rms + b_all[1])));
        hq.z = __fdividef(1.0f, 1.0f + __expf(-(s24[2] * rms + b_all[2])));
        hq.w = __fdividef(1.0f, 1.0f + __expf(-(s24[3] * rms + b_all[3])));
        *reinterpret_cast<float4*>(g_hpre + pix * 4) = hq;
    }
    {
        float4 hq;
        hq.x = __fdividef(2.0f, 1.0f + __expf(-(s24[20] * rms + b_all[20])));
        hq.y = __fdividef(2.0f, 1.0f + __expf(-(s24[21] * rms + b_all[21])));
        hq.z = __fdividef(2.0f, 1.0f + __expf(-(s24[22] * rms + b_all[22])));
        hq.w = __fdividef(2.0f, 1.0f + __expf(-(s24[23] * rms + b_all[23])));
        *reinterpret_cast<float4*>(g_hpost + pix * 4) = hq;
    }

    {
        float v[16];
#pragma unroll
        for (int j = 0; j < 16; j++) v[j] = s24[4 + j] * rms + b_all[4 + j];
        float m = v[0];
#pragma unroll
        for (int j = 1; j < 16; j++) m = fmaxf(m, v[j]);
#pragma unroll
        for (int j = 0; j < 16; j++) v[j] = __expf(v[j] - m);
#pragma unroll 1
        for (int it = 0; it < 20; ++it) {
#pragma unroll
            for (int t = 0; t < 4; t++) {
                const float cs = v[t] + v[4 + t] + v[8 + t] + v[12 + t];
                const float inv = __fdividef(1.0f, cs + 1e-6f);
                v[t] *= inv; v[4 + t] *= inv; v[8 + t] *= inv; v[12 + t] *= inv;
            }
#pragma unroll
            for (int s = 0; s < 4; s++) {
                const float rs = v[4 * s] + v[4 * s + 1] + v[4 * s + 2] + v[4 * s + 3];
                const float inv = __fdividef(1.0f, rs + 1e-6f);
                v[4 * s] *= inv; v[4 * s + 1] *= inv; v[4 * s + 2] *= inv; v[4 * s + 3] *= inv;
            }
        }
        float4* hq = reinterpret_cast<float4*>(g_hres + pix * 16);
        hq[0] = make_float4(v[0], v[1], v[2], v[3]);
        hq[1] = make_float4(v[4], v[5], v[6], v[7]);
        hq[2] = make_float4(v[8], v[9], v[10], v[11]);
        hq[3] = make_float4(v[12], v[13], v[14], v[15]);
    }
}

// ---------------------------------------------------------------------------
// Kernel 2: x_pre = sum_s h_pre[s]*x[s,:], bf16 hi/lo output. (unchanged)
// ---------------------------------------------------------------------------
constexpr int XP_STRIDE = 261;
constexpr int XPRE_SMEM = 64 * XP_STRIDE * 4;   // 66816 B

__global__ void __launch_bounds__(256) xpre_kernel(const float* __restrict__ x)
{
    extern __shared__ __align__(16) float sx[];
    __shared__ float s_hp[64][4];

    const int tid = threadIdx.x;
    const size_t pixbase = (size_t)blockIdx.x * 64;

#pragma unroll
    for (int k = 0; k < 16; k++) {
        const int e4 = tid + k * 256;
        const int p = e4 >> 6, f4 = (e4 & 63) * 4;
        const float4 v = *reinterpret_cast<const float4*>(&x[(pixbase + p) * SCn + f4]);
        sx[p * XP_STRIDE + f4 + 0] = v.x;
        sx[p * XP_STRIDE + f4 + 1] = v.y;
        sx[p * XP_STRIDE + f4 + 2] = v.z;
        sx[p * XP_STRIDE + f4 + 3] = v.w;
    }
    if (tid < 64) {
        const float4 h = *reinterpret_cast<const float4*>(g_hpre + (pixbase + tid) * 4);
        s_hp[tid][0] = h.x; s_hp[tid][1] = h.y; s_hp[tid][2] = h.z; s_hp[tid][3] = h.w;
    }
    __syncthreads();

    const int p = tid & 63, ch2 = tid >> 6;
    const float h0 = s_hp[p][0], h1 = s_hp[p][1], h2 = s_hp[p][2], h3 = s_hp[p][3];
    const float* row = sx + p * XP_STRIDE + ch2 * 16;

    uint32_t uhi[8], ulo[8];
#pragma unroll
    for (int j2 = 0; j2 < 8; j2++) {
        uint32_t h_pack = 0, l_pack = 0;
#pragma unroll
        for (int half = 0; half < 2; half++) {
            const int c = j2 * 2 + half;
            const float v = h0 * row[c] + h1 * row[64 + c] + h2 * row[128 + c] + h3 * row[192 + c];
            const __nv_bfloat16 hi = __float2bfloat16(v);
            const __nv_bfloat16 lo = __float2bfloat16(v - __bfloat162float(hi));
            h_pack |= (uint32_t)__bfloat16_as_ushort(hi) << (16 * half);
            l_pack |= (uint32_t)__bfloat16_as_ushort(lo) << (16 * half);
        }
        uhi[j2] = h_pack; ulo[j2] = l_pack;
    }
    uint4* dst = reinterpret_cast<uint4*>(g_xpb + (pixbase + p) * 128);
    dst[ch2 * 2 + 0] = make_uint4(uhi[0], uhi[1], uhi[2], uhi[3]);
    dst[ch2 * 2 + 1] = make_uint4(uhi[4], uhi[5], uhi[6], uhi[7]);
    dst[8 + ch2 * 2 + 0] = make_uint4(ulo[0], ulo[1], ulo[2], ulo[3]);
    dst[8 + ch2 * 2 + 1] = make_uint4(ulo[4], ulo[5], ulo[6], ulo[7]);
}

// ---------------------------------------------------------------------------
// Kernel 3: conv via mma.sync bf16, RAW A rows + per-lane kx shift addressing,
// cp.async pipelined B ring. One CTA per image row.
// ---------------------------------------------------------------------------
constexpr int AROW = 272;                   // bytes per pixel slot (17 x 16B, conflict-free)
constexpr int AKY  = 130 * AROW;            // 35360 B per raw input row
constexpr int A_RAW = 3 * AKY;              // 106080
constexpr int BST  = 784;                   // B row stride bytes (49 x 16B)
constexpr int BBUF = 64 * BST;              // 50176
constexpr int CONV_SMEM = A_RAW + 2 * BBUF; // 206432

__global__ void __launch_bounds__(256, 1) conv_kernel(const float* __restrict__ x,
                                                      float* __restrict__ out)
{
    extern __shared__ __align__(16) char smem[];
    char* s_a = smem;
    const uint32_t sa = smem_u32(smem);
    const uint32_t sb = sa + A_RAW;

    const int tid = threadIdx.x;
    const int wid = tid >> 5, lane = tid & 31;
    const int y = blockIdx.x, b = blockIdx.y;

    // ---- prologue: zero pads / edge rows, cp.async A rows + B stage 0 ----
    {
        const uint4 z = make_uint4(0, 0, 0, 0);
        if (tid < 102) {   // 3 ky x (slot0 + slot129) x 17 uint4
            const int ky = tid / 34, j = tid % 34;
            const int p = (j < 17) ? 0 : 129, q = (j < 17) ? j : j - 17;
            *reinterpret_cast<uint4*>(s_a + ky * AKY + p * AROW + q * 16) = z;
        }
        if (y == 0)
            for (int e = tid; e < AKY / 16; e += 256)
                *reinterpret_cast<uint4*>(s_a + e * 16) = z;
        if (y == 127)
            for (int e = tid; e < AKY / 16; e += 256)
                *reinterpret_cast<uint4*>(s_a + 2 * AKY + e * 16) = z;
    }
#pragma unroll
    for (int i = 0; i < 24; i++) {          // A payload: 3 rows x 128 px x 16 uint4
        const int e = tid + i * 256;
        const int ky = e >> 11, rem = e & 2047;
        const int p = rem >> 4, q = rem & 15;
        const int y2 = y + ky - 1;
        if ((unsigned)y2 < 128u)
            cp16(sa + ky * AKY + (p + 1) * AROW + q * 16,
                 g_xpb + (((size_t)(b * 128 + y2) * 128 + p) * 128) + q * 8);
    }
#pragma unroll
    for (int i = 0; i < 12; i++) {          // B stage 0
        const int e = tid + i * 256;
        const int co = e / 48, u = e - co * 48;
        cp16(sb + co * BST + u * 16, g_wb + 0 * 24576 + co * 384 + u * 8);
    }
    CP_COMMIT();

    float d[8][4];
#pragma unroll
    for (int t = 0; t < 8; t++)
#pragma unroll
        for (int j = 0; j < 4; j++) d[t][j] = 0.f;

    const uint32_t a_lane = sa + (uint32_t)(16 * wid + (lane & 15)) * AROW + (uint32_t)((lane >> 4) << 4);
    uint32_t b_off[4];
#pragma unroll
    for (int t = 0; t < 4; t++)
        b_off[t] = sb + (uint32_t)(16 * t + (lane & 7) + ((lane >> 4) << 3)) * BST
                      + (uint32_t)(((lane >> 3) & 1) << 4);

#pragma unroll 1
    for (int s = 0; s < 6; s++) {           // stage = ky*2 + pass
        CP_WAIT0();
        __syncthreads();
        if (s < 5) {                        // prefetch next B into other buffer
            const uint32_t dstb = sb + (uint32_t)(((s + 1) & 1) * BBUF);
            const __nv_bfloat16* srcb = g_wb + (size_t)(s + 1) * 24576;
#pragma unroll
            for (int i = 0; i < 12; i++) {
                const int e = tid + i * 256;
                const int co = e / 48, u = e - co * 48;
                cp16(dstb + co * BST + u * 16, srcb + co * 384 + u * 8);
            }
            CP_COMMIT();
        }
        const uint32_t a_base = a_lane + (uint32_t)((s >> 1) * AKY);
        const uint32_t bshift = (uint32_t)((s & 1) * BBUF);
#pragma unroll 4
        for (int kk = 0; kk < 24; kk++) {
            const int kx = kk >> 3, c16 = kk & 7;
            uint32_t a0, a1, a2, a3;
            ldsm4(a0, a1, a2, a3, a_base + kx * AROW + c16 * 32);
#pragma unroll
            for (int t = 0; t < 4; t++) {
                uint32_t b0, b1, b2, b3;
                ldsm4(b0, b1, b2, b3, b_off[t] + bshift + kk * 32);
                mma16816(d[2 * t],     a0, a1, a2, a3, b0, b1);
                mma16816(d[2 * t + 1], a0, a1, a2, a3, b2, b3);
            }
        }
    }

    __syncthreads();
    // ---- write layer_out to smem [128][65] (reuse A region) ----
    float* s_l = reinterpret_cast<float*>(smem);
    {
        const int gid = lane >> 2, tig = lane & 3;
#pragma unroll
        for (int t = 0; t < 4; t++)
#pragma unroll
            for (int h = 0; h < 2; h++) {
                const int nt = 2 * t + h, nb = 16 * t + 8 * h;
                s_l[(16 * wid + gid) * 65 + nb + 2 * tig]     = d[nt][0];
                s_l[(16 * wid + gid) * 65 + nb + 2 * tig + 1] = d[nt][1];
                s_l[(16 * wid + gid + 8) * 65 + nb + 2 * tig]     = d[nt][2];
                s_l[(16 * wid + gid + 8) * 65 + nb + 2 * tig + 1] = d[nt][3];
            }
    }
    __syncthreads();

    // ---- epilogue: out = einsum(h_res, x) + h_post * layer_out ----
    const size_t rowpix = ((size_t)b * 128 + y) * 128;
#pragma unroll 1
    for (int pp = 0; pp < 16; ++pp) {
        const int m = wid * 16 + pp;
        const size_t pix = rowpix + m;
        const float* xp = x + pix * SCn;
        const float4* hq = reinterpret_cast<const float4*>(g_hres + pix * 16);
        const float4 h0 = hq[0], h1 = hq[1], h2 = hq[2], h3 = hq[3];
        const float4 hpst = *reinterpret_cast<const float4*>(g_hpost + pix * 4);
        const float* lrow = s_l + m * 65;
        float* op = out + pix * SCn;
#pragma unroll
        for (int p2 = 0; p2 < 2; ++p2) {
            const int c = p2 * 32 + lane;
            const float l  = lrow[c];
            const float t0 = xp[c];
            const float t1 = xp[64 + c];
            const float t2 = xp[128 + c];
            const float t3 = xp[192 + c];
            op[c]       = h0.x * t0 + h0.y * t1 + h0.z * t2 + h0.w * t3 + hpst.x * l;
            op[64 + c]  = h1.x * t0 + h1.y * t1 + h1.z * t2 + h1.w * t3 + hpst.y * l;
            op[128 + c] = h2.x * t0 + h2.y * t1 + h2.z * t2 + h2.w * t3 + hpst.z * l;
            op[192 + c] = h3.x * t0 + h3.y * t1 + h3.z * t2 + h3.w * t3 + hpst.w * l;
        }
    }
}

// ---------------------------------------------------------------------------
extern "C" void kernel_launch(void* const* d_in, const int* in_sizes, int n_in,
                              void* d_out, int out_size)
{
    const float* x       = (const float*)d_in[0];
    const float* w_pre   = (const float*)d_in[1];
    const float* w_post  = (const float*)d_in[2];
    const float* w_res   = (const float*)d_in[3];
    const float* b_pre   = (const float*)d_in[4];
    const float* b_res   = (const float*)d_in[5];
    const float* b_post  = (const float*)d_in[6];
    const float* a_pre   = (const float*)d_in[7];
    const float* a_res   = (const float*)d_in[8];
    const float* a_post  = (const float*)d_in[9];
    const float* rms_w   = (const float*)d_in[10];
    const float* conv_w  = (const float*)d_in[11];
    float* out = (float*)d_out;

    wprep_kernel<<<(6 * 64 * 384 + 255) / 256, 256>>>(conv_w);

    cudaFuncSetAttribute(proj_kernel, cudaFuncAttributeMaxDynamicSharedMemorySize, PROJ_SMEM);
    proj_kernel<<<NPIX / 256, 256, PROJ_SMEM>>>(x, w_pre, w_post, w_res,
                                                b_pre, b_res, b_post,
                                                a_pre, a_res, a_post, rms_w);

    cudaFuncSetAttribute(xpre_kernel, cudaFuncAttributeMaxDynamicSharedMemorySize, XPRE_SMEM);
    xpre_kernel<<<NPIX / 64, 256, XPRE_SMEM>>>(x);

    cudaFuncSetAttribute(conv_kernel, cudaFuncAttributeMaxDynamicSharedMemorySize, CONV_SMEM);
    conv_kernel<<<dim3(Hn, Bn), 256, CONV_SMEM>>>(x, out);
}

// round 7
// speedup vs baseline: 1.9553x; 1.1449x over previous
#include <cuda_runtime.h>
#include <cuda_bf16.h>
#include <cstdint>

#define FULL 0xffffffffu

constexpr int Bn = 16, Hn = 128, Wn = 128, Sn = 4, Cn = 64;
constexpr int SCn = Sn * Cn;                // 256
constexpr int NPIX = Bn * Hn * Wn;          // 262144

// Scratch (static device arrays -- allocation-free rule)
__device__ __nv_bfloat16 g_xpb[(size_t)NPIX * 128];        // [pix][hi(64)|lo(64)] bf16
__device__ __align__(16) float g_hpost[(size_t)NPIX * Sn]; // [pix][4]
__device__ __align__(16) float g_hpre[(size_t)NPIX * Sn];  // [pix][4]
__device__ __align__(16) float g_hres[(size_t)NPIX * 16];  // [pix][16] (sinkhorn'd)
__device__ __nv_bfloat16 g_wb[6 * 64 * 384];               // [stage=ky*2+pass][co][k=384]

union F2U { float2 f; unsigned long long u; };

__device__ __forceinline__ unsigned long long pack2(float v) {
    F2U t; t.f = make_float2(v, v); return t.u;
}
__device__ __forceinline__ void ffma2(unsigned long long& d, unsigned long long a, unsigned long long b) {
    asm("fma.rn.f32x2 %0, %1, %2, %0;" : "+l"(d) : "l"(a), "l"(b));
}
__device__ __forceinline__ uint32_t smem_u32(const void* p) {
    uint32_t a;
    asm("{ .reg .u64 t; cvta.to.shared.u64 t, %1; cvt.u32.u64 %0, t; }" : "=r"(a) : "l"(p));
    return a;
}
__device__ __forceinline__ void ldsm4(uint32_t& r0, uint32_t& r1, uint32_t& r2, uint32_t& r3, uint32_t addr) {
    asm volatile("ldmatrix.sync.aligned.m8n8.x4.shared.b16 {%0,%1,%2,%3}, [%4];"
                 : "=r"(r0), "=r"(r1), "=r"(r2), "=r"(r3) : "r"(addr));
}
__device__ __forceinline__ void mma16816(float* d, uint32_t a0, uint32_t a1, uint32_t a2, uint32_t a3,
                                         uint32_t b0, uint32_t b1) {
    asm volatile("mma.sync.aligned.m16n8k16.row.col.f32.bf16.bf16.f32 "
                 "{%0,%1,%2,%3}, {%4,%5,%6,%7}, {%8,%9}, {%0,%1,%2,%3};"
                 : "+f"(d[0]), "+f"(d[1]), "+f"(d[2]), "+f"(d[3])
                 : "r"(a0), "r"(a1), "r"(a2), "r"(a3), "r"(b0), "r"(b1));
}
__device__ __forceinline__ void cp16(uint32_t smaddr, const void* g) {
    asm volatile("cp.async.cg.shared.global [%0], [%1], 16;" :: "r"(smaddr), "l"(g));
}
#define CP_COMMIT() asm volatile("cp.async.commit_group;" ::: "memory")
#define CP_WAIT0()  asm volatile("cp.async.wait_group 0;" ::: "memory")
#define CP_WAIT1()  asm volatile("cp.async.wait_group 1;" ::: "memory")

// ---------------------------------------------------------------------------
// Kernel 0: weight prep (unchanged)
// ---------------------------------------------------------------------------
__global__ void wprep_kernel(const float* __restrict__ conv_w)
{
    const int e = blockIdx.x * 256 + threadIdx.x;
    if (e >= 6 * 64 * 384) return;
    const int tile = e / (64 * 384);
    const int rem = e - tile * (64 * 384);
    const int co = rem / 384, k = rem - co * 384;
    const int ky = tile >> 1, pass = tile & 1;
    const int kx = k >> 7, ci = k & 63;
    const float w = conv_w[((size_t)(ky * 3 + kx) * 64 + ci) * 64 + co];
    const __nv_bfloat16 hi = __float2bfloat16(w);
    __nv_bfloat16 v = hi;
    if (pass) v = __float2bfloat16(w - __bfloat162float(hi));
    g_wb[e] = v;
}

// ---------------------------------------------------------------------------
// Kernel 1: projections + inline Sinkhorn. ONE THREAD PER PIXEL. (unchanged)
// ---------------------------------------------------------------------------
constexpr int SX_STRIDE = 33;
constexpr int SX_FLOATS = 256 * SX_STRIDE;
constexpr int SW_FLOATS = 256 * 24;
constexpr int PROJ_SMEM = (SX_FLOATS + SW_FLOATS) * 4;

__global__ void __launch_bounds__(256) proj_kernel(
    const float* __restrict__ x,
    const float* __restrict__ w_pre, const float* __restrict__ w_post, const float* __restrict__ w_res,
    const float* __restrict__ b_pre, const float* __restrict__ b_res, const float* __restrict__ b_post,
    const float* __restrict__ alpha_pre, const float* __restrict__ alpha_res, const float* __restrict__ alpha_post,
    const float* __restrict__ rms_w)
{
    extern __shared__ __align__(16) float dsm[];
    float* s_x = dsm;
    float* s_w = dsm + SX_FLOATS;
    __shared__ float b_all[24];

    const int tid = threadIdx.x;
    {
        const int f = tid;
        const float rw = rms_w[f];
        const float apre = alpha_pre[0], ares = alpha_res[0], apost = alpha_post[0];
#pragma unroll
        for (int o = 0; o < 4; o++)  s_w[f * 24 + o]      = apre  * w_pre[o * SCn + f]  * rw;
#pragma unroll
        for (int o = 0; o < 16; o++) s_w[f * 24 + 4 + o]  = ares  * w_res[o * SCn + f]  * rw;
#pragma unroll
        for (int o = 0; o < 4; o++)  s_w[f * 24 + 20 + o] = apost * w_post[o * SCn + f] * rw;
        if (tid < 4)       b_all[tid] = b_pre[tid];
        else if (tid < 20) b_all[tid] = b_res[tid - 4];
        else if (tid < 24) b_all[tid] = b_post[tid - 20];
    }

    const size_t pixbase = (size_t)blockIdx.x * 256;
    const size_t pix = pixbase + tid;
    const float* xb = x + pixbase * SCn;

    unsigned long long acc[12];
#pragma unroll
    for (int j = 0; j < 12; j++) acc[j] = 0ull;
    float ss = 0.f;

    float4 rr[8];
#pragma unroll
    for (int k = 0; k < 8; k++) {
        const int e4 = tid + k * 256;
        const int p = e4 >> 3, f4 = (e4 & 7) * 4;
        rr[k] = *reinterpret_cast<const float4*>(&xb[p * SCn + 0 * 32 + f4]);
    }

#pragma unroll 1
    for (int ch = 0; ch < 8; ch++) {
        __syncthreads();
#pragma unroll
        for (int k = 0; k < 8; k++) {
            const int e4 = tid + k * 256;
            const int p = e4 >> 3, f4 = (e4 & 7) * 4;
            s_x[p * SX_STRIDE + f4 + 0] = rr[k].x;
            s_x[p * SX_STRIDE + f4 + 1] = rr[k].y;
            s_x[p * SX_STRIDE + f4 + 2] = rr[k].z;
            s_x[p * SX_STRIDE + f4 + 3] = rr[k].w;
        }
        __syncthreads();
        if (ch < 7) {
#pragma unroll
            for (int k = 0; k < 8; k++) {
                const int e4 = tid + k * 256;
                const int p = e4 >> 3, f4 = (e4 & 7) * 4;
                rr[k] = *reinterpret_cast<const float4*>(&xb[p * SCn + (ch + 1) * 32 + f4]);
            }
        }
#pragma unroll
        for (int f = 0; f < 32; f++) {
            const float xf = s_x[tid * SX_STRIDE + f];
            ss = fmaf(xf, xf, ss);
            const unsigned long long xx = pack2(xf);
            const ulonglong2* w2 = reinterpret_cast<const ulonglong2*>(s_w + (ch * 32 + f) * 24);
#pragma unroll
            for (int q = 0; q < 6; q++) {
                const ulonglong2 w = w2[q];
                ffma2(acc[2 * q],     xx, w.x);
                ffma2(acc[2 * q + 1], xx, w.y);
            }
        }
    }

    const float rms = rsqrtf(ss * (1.0f / 256.0f) + 1.1920929e-07f);
    float s24[24];
#pragma unroll
    for (int j = 0; j < 12; j++) {
        F2U t; t.u = acc[j];
        s24[2 * j] = t.f.x; s24[2 * j + 1] = t.f.y;
    }

    {
        float4 hq;
        hq.x = __fdividef(1.0f, 1.0f + __expf(-(s24[0] * rms + b_all[0])));
        hq.y = __fdividef(1.0f, 1.0f + __expf(-(s24[1] * rms + b_all[1])));
        hq.z = __fdividef(1.0f, 1.0f + __expf(-(s24[2] * rms + b_all[2])));
        hq.w = __fdividef(1.0f, 1.0f + __expf(-(s24[3] * rms + b_all[3])));
        *reinterpret_cast<float4*>(g_hpre + pix * 4) = hq;
    }
    {
        float4 hq;
        hq.x = __fdividef(2.0f, 1.0f + __expf(-(s24[20] * rms + b_all[20])));
        hq.y = __fdividef(2.0f, 1.0f + __expf(-(s24[21] * rms + b_all[21])));
        hq.z = __fdividef(2.0f, 1.0f + __expf(-(s24[22] * rms + b_all[22])));
        hq.w = __fdividef(2.0f, 1.0f + __expf(-(s24[23] * rms + b_all[23])));
        *reinterpret_cast<float4*>(g_hpost + pix * 4) = hq;
    }

    {
        float v[16];
#pragma unroll
        for (int j = 0; j < 16; j++) v[j] = s24[4 + j] * rms + b_all[4 + j];
        float m = v[0];
#pragma unroll
        for (int j = 1; j < 16; j++) m = fmaxf(m, v[j]);
#pragma unroll
        for (int j = 0; j < 16; j++) v[j] = __expf(v[j] - m);
#pragma unroll 1
        for (int it = 0; it < 20; ++it) {
#pragma unroll
            for (int t = 0; t < 4; t++) {
                const float cs = v[t] + v[4 + t] + v[8 + t] + v[12 + t];
                const float inv = __fdividef(1.0f, cs + 1e-6f);
                v[t] *= inv; v[4 + t] *= inv; v[8 + t] *= inv; v[12 + t] *= inv;
            }
#pragma unroll
            for (int s = 0; s < 4; s++) {
                const float rs = v[4 * s] + v[4 * s + 1] + v[4 * s + 2] + v[4 * s + 3];
                const float inv = __fdividef(1.0f, rs + 1e-6f);
                v[4 * s] *= inv; v[4 * s + 1] *= inv; v[4 * s + 2] *= inv; v[4 * s + 3] *= inv;
            }
        }
        float4* hq = reinterpret_cast<float4*>(g_hres + pix * 16);
        hq[0] = make_float4(v[0], v[1], v[2], v[3]);
        hq[1] = make_float4(v[4], v[5], v[6], v[7]);
        hq[2] = make_float4(v[8], v[9], v[10], v[11]);
        hq[3] = make_float4(v[12], v[13], v[14], v[15]);
    }
}

// ---------------------------------------------------------------------------
// Kernel 2: x_pre -> bf16 hi/lo (unchanged)
// ---------------------------------------------------------------------------
constexpr int XP_STRIDE = 261;
constexpr int XPRE_SMEM = 64 * XP_STRIDE * 4;

__global__ void __launch_bounds__(256) xpre_kernel(const float* __restrict__ x)
{
    extern __shared__ __align__(16) float sx[];
    __shared__ float s_hp[64][4];

    const int tid = threadIdx.x;
    const size_t pixbase = (size_t)blockIdx.x * 64;

#pragma unroll
    for (int k = 0; k < 16; k++) {
        const int e4 = tid + k * 256;
        const int p = e4 >> 6, f4 = (e4 & 63) * 4;
        const float4 v = *reinterpret_cast<const float4*>(&x[(pixbase + p) * SCn + f4]);
        sx[p * XP_STRIDE + f4 + 0] = v.x;
        sx[p * XP_STRIDE + f4 + 1] = v.y;
        sx[p * XP_STRIDE + f4 + 2] = v.z;
        sx[p * XP_STRIDE + f4 + 3] = v.w;
    }
    if (tid < 64) {
        const float4 h = *reinterpret_cast<const float4*>(g_hpre + (pixbase + tid) * 4);
        s_hp[tid][0] = h.x; s_hp[tid][1] = h.y; s_hp[tid][2] = h.z; s_hp[tid][3] = h.w;
    }
    __syncthreads();

    const int p = tid & 63, ch2 = tid >> 6;
    const float h0 = s_hp[p][0], h1 = s_hp[p][1], h2 = s_hp[p][2], h3 = s_hp[p][3];
    const float* row = sx + p * XP_STRIDE + ch2 * 16;

    uint32_t uhi[8], ulo[8];
#pragma unroll
    for (int j2 = 0; j2 < 8; j2++) {
        uint32_t h_pack = 0, l_pack = 0;
#pragma unroll
        for (int half = 0; half < 2; half++) {
            const int c = j2 * 2 + half;
            const float v = h0 * row[c] + h1 * row[64 + c] + h2 * row[128 + c] + h3 * row[192 + c];
            const __nv_bfloat16 hi = __float2bfloat16(v);
            const __nv_bfloat16 lo = __float2bfloat16(v - __bfloat162float(hi));
            h_pack |= (uint32_t)__bfloat16_as_ushort(hi) << (16 * half);
            l_pack |= (uint32_t)__bfloat16_as_ushort(lo) << (16 * half);
        }
        uhi[j2] = h_pack; ulo[j2] = l_pack;
    }
    uint4* dst = reinterpret_cast<uint4*>(g_xpb + (pixbase + p) * 128);
    dst[ch2 * 2 + 0] = make_uint4(uhi[0], uhi[1], uhi[2], uhi[3]);
    dst[ch2 * 2 + 1] = make_uint4(uhi[4], uhi[5], uhi[6], uhi[7]);
    dst[8 + ch2 * 2 + 0] = make_uint4(ulo[0], ulo[1], ulo[2], ulo[3]);
    dst[8 + ch2 * 2 + 1] = make_uint4(ulo[4], ulo[5], ulo[6], ulo[7]);
}

// ---------------------------------------------------------------------------
// Kernel 3: conv via mma.sync bf16 -- 64px CTAs, 2 CTAs/SM, 3-slot B chunk
// ring with cp.async depth-2 prefetch. 8 warps = 4 M16-tiles x 2 N32-halves.
// ---------------------------------------------------------------------------
constexpr int AROW = 272;                     // bytes per px slot (17 x 16B)
constexpr int AKY  = 66 * AROW;               // 17952 per raw input row (64 + 2 halo)
constexpr int A_RAW = 3 * AKY;                // 53856
constexpr int BROW = 272;                     // B chunk row stride (16 uint4 payload + pad)
constexpr int BBUF1 = 64 * BROW;              // 17408
constexpr int CONV_SMEM = A_RAW + 3 * BBUF1;  // 106080

__device__ __forceinline__ void issue_b_chunk(uint32_t sb, int c, int tid)
{
    const int stage = c / 3, kc = c - stage * 3;
    const uint32_t dst = sb + (uint32_t)((c % 3) * BBUF1);
    const __nv_bfloat16* src = g_wb + (size_t)stage * 24576 + kc * 128;
#pragma unroll
    for (int i = 0; i < 4; i++) {
        const int e = tid + i * 256;
        const int row = e >> 4, q = e & 15;
        cp16(dst + row * BROW + q * 16, src + row * 384 + q * 8);
    }
}

__global__ void __launch_bounds__(256, 2) conv_kernel(const float* __restrict__ x,
                                                      float* __restrict__ out)
{
    extern __shared__ __align__(16) char smem[];
    char* s_a = smem;
    const uint32_t sa = smem_u32(smem);
    const uint32_t sb = sa + A_RAW;

    const int tid = threadIdx.x;
    const int wid = tid >> 5, lane = tid & 31;
    const int wm = wid & 3, wn = wid >> 2;       // M-tile, N-half
    const int xh = blockIdx.x;                   // 0/1: px base 64*xh
    const int y = blockIdx.y, b = blockIdx.z;

    // ---- prologue: A (3 raw rows, halo slots) + B chunks 0,1 ----
    {
        const uint4 z = make_uint4(0, 0, 0, 0);
#pragma unroll 1
        for (int e = tid; e < 3 * 66 * 16; e += 256) {
            const int ky = e / 1056, rem = e - ky * 1056;
            const int p = rem >> 4, q = rem & 15;
            const int y2 = y + ky - 1;
            const int gx = xh * 64 + p - 1;
            const uint32_t dst = sa + (uint32_t)(ky * AKY + p * AROW + q * 16);
            if ((unsigned)y2 < 128u && (unsigned)gx < 128u)
                cp16(dst, g_xpb + (((size_t)(b * 128 + y2) * 128 + gx) * 128) + q * 8);
            else
                *reinterpret_cast<uint4*>(s_a + (ky * AKY + p * AROW + q * 16)) = z;
        }
    }
    issue_b_chunk(sb, 0, tid);
    CP_COMMIT();                    // G0 = A + chunk0
    issue_b_chunk(sb, 1, tid);
    CP_COMMIT();                    // G1 = chunk1

    float d[4][4];
#pragma unroll
    for (int t = 0; t < 4; t++)
#pragma unroll
        for (int j = 0; j < 4; j++) d[t][j] = 0.f;

    // per-lane fragment addresses
    const uint32_t a_lane = sa + (uint32_t)((16 * wm + (lane & 15)) * AROW) + (uint32_t)((lane >> 4) << 4);
    uint32_t b_lane[2];
#pragma unroll
    for (int t = 0; t < 2; t++)
        b_lane[t] = sb + (uint32_t)((32 * wn + 16 * t + (lane & 7) + ((lane >> 4) << 3)) * BROW)
                       + (uint32_t)(((lane >> 3) & 1) << 4);

#pragma unroll 1
    for (int c = 0; c < 18; c++) {
        if (c < 17) { CP_WAIT1(); } else { CP_WAIT0(); }
        __syncthreads();
        if (c < 16) { issue_b_chunk(sb, c + 2, tid); CP_COMMIT(); }

        const int stage = c / 3, kc = c - stage * 3;   // kc == kx
        const int ky = stage >> 1;
        // A slot shift: input px = out_px + kx - 1 -> slot = 16*wm + row + kc
        const uint32_t a_base = a_lane + (uint32_t)(ky * AKY + kc * AROW);
        const uint32_t b_base = (uint32_t)((c % 3) * BBUF1);

#pragma unroll
        for (int j = 0; j < 8; j++) {                  // 8 k16 sub-chunks
            uint32_t a0, a1, a2, a3;
            ldsm4(a0, a1, a2, a3, a_base + j * 32);
#pragma unroll
            for (int t = 0; t < 2; t++) {
                uint32_t b0, b1, b2, b3;
                ldsm4(b0, b1, b2, b3, b_lane[t] + b_base + j * 32);
                mma16816(d[2 * t],     a0, a1, a2, a3, b0, b1);
                mma16816(d[2 * t + 1], a0, a1, a2, a3, b2, b3);
            }
        }
    }

    __syncthreads();
    // ---- layer_out -> smem [64][65] (reuse A region) ----
    float* s_l = reinterpret_cast<float*>(smem);
    {
        const int gid = lane >> 2, tig = lane & 3;
#pragma unroll
        for (int t = 0; t < 4; t++) {
            const int nb = 32 * wn + 8 * t;
            s_l[(16 * wm + gid) * 65 + nb + 2 * tig]     = d[t][0];
            s_l[(16 * wm + gid) * 65 + nb + 2 * tig + 1] = d[t][1];
            s_l[(16 * wm + gid + 8) * 65 + nb + 2 * tig]     = d[t][2];
            s_l[(16 * wm + gid + 8) * 65 + nb + 2 * tig + 1] = d[t][3];
        }
    }
    __syncthreads();

    // ---- epilogue: out = einsum(h_res, x) + h_post * layer_out ----
    const size_t rowpix = ((size_t)b * 128 + y) * 128 + xh * 64;
#pragma unroll 1
    for (int pp = 0; pp < 8; ++pp) {
        const int m = wid * 8 + pp;
        const size_t pix = rowpix + m;
        const float* xp = x + pix * SCn;
        const float4* hq = reinterpret_cast<const float4*>(g_hres + pix * 16);
        const float4 h0 = hq[0], h1 = hq[1], h2 = hq[2], h3 = hq[3];
        const float4 hpst = *reinterpret_cast<const float4*>(g_hpost + pix * 4);
        const float* lrow = s_l + m * 65;
        float* op = out + pix * SCn;
#pragma unroll
        for (int p2 = 0; p2 < 2; ++p2) {
            const int c = p2 * 32 + lane;
            const float l  = lrow[c];
            const float t0 = xp[c];
            const float t1 = xp[64 + c];
            const float t2 = xp[128 + c];
            const float t3 = xp[192 + c];
            op[c]       = h0.x * t0 + h0.y * t1 + h0.z * t2 + h0.w * t3 + hpst.x * l;
            op[64 + c]  = h1.x * t0 + h1.y * t1 + h1.z * t2 + h1.w * t3 + hpst.y * l;
            op[128 + c] = h2.x * t0 + h2.y * t1 + h2.z * t2 + h2.w * t3 + hpst.z * l;
            op[192 + c] = h3.x * t0 + h3.y * t1 + h3.z * t2 + h3.w * t3 + hpst.w * l;
        }
    }
}

// ---------------------------------------------------------------------------
extern "C" void kernel_launch(void* const* d_in, const int* in_sizes, int n_in,
                              void* d_out, int out_size)
{
    const float* x       = (const float*)d_in[0];
    const float* w_pre   = (const float*)d_in[1];
    const float* w_post  = (const float*)d_in[2];
    const float* w_res   = (const float*)d_in[3];
    const float* b_pre   = (const float*)d_in[4];
    const float* b_res   = (const float*)d_in[5];
    const float* b_post  = (const float*)d_in[6];
    const float* a_pre   = (const float*)d_in[7];
    const float* a_res   = (const float*)d_in[8];
    const float* a_post  = (const float*)d_in[9];
    const float* rms_w   = (const float*)d_in[10];
    const float* conv_w  = (const float*)d_in[11];
    float* out = (float*)d_out;

    wprep_kernel<<<(6 * 64 * 384 + 255) / 256, 256>>>(conv_w);

    cudaFuncSetAttribute(proj_kernel, cudaFuncAttributeMaxDynamicSharedMemorySize, PROJ_SMEM);
    proj_kernel<<<NPIX / 256, 256, PROJ_SMEM>>>(x, w_pre, w_post, w_res,
                                                b_pre, b_res, b_post,
                                                a_pre, a_res, a_post, rms_w);

    cudaFuncSetAttribute(xpre_kernel, cudaFuncAttributeMaxDynamicSharedMemorySize, XPRE_SMEM);
    xpre_kernel<<<NPIX / 64, 256, XPRE_SMEM>>>(x);

    cudaFuncSetAttribute(conv_kernel, cudaFuncAttributeMaxDynamicSharedMemorySize, CONV_SMEM);
    conv_kernel<<<dim3(2, Hn, Bn), 256, CONV_SMEM>>>(x, out);
}